// round 3
// baseline (speedup 1.0000x reference)
#include <cuda_runtime.h>
#include <cuda_fp16.h>
#include <math.h>

#define NN 50000
#define NE 800000
#define DD 128
#define NG 3
#define NTILES ((NN + 63) / 64)   // 782
#define NSCAN 13
#define GEMM_BLOCKS 98
#define ZP 132
#define WP 132

typedef unsigned long long ull;

// ---------------- scratch ----------------------------------------------------
__device__ int    d_deg[NG][NN];
__device__ int    d_start[NG][NN + 1];
__device__ int    d_cursor[NG][NN];
__device__ int    d_srcs[NG][NE];
__device__ float  d_dinv[NG][NN];
__device__ __half d_y[NG][NN * DD];    // fp16 dinv[n]*x[n]
__device__ float  d_z[NG][NN * DD];    // aggregated features (fp32)
__device__ float  d_gsum[NG][DD];
__device__ int    d_bsum[NG][16];

// ---------------- helpers ----------------------------------------------------
__device__ __forceinline__ ull ffma2(ull a, ull b, ull c) {
    ull d;
    asm("fma.rn.f32x2 %0, %1, %2, %3;" : "=l"(d) : "l"(a), "l"(b), "l"(c));
    return d;
}
__device__ __forceinline__ void unpack64(ull p, float& lo, float& hi) {
    asm("mov.b64 {%0, %1}, %2;" : "=f"(lo), "=f"(hi) : "l"(p));
}

// ---------------- prep kernels -----------------------------------------------
__global__ void zero_kernel() {
    int i = blockIdx.x * blockDim.x + threadIdx.x;
    int stride = gridDim.x * blockDim.x;
    for (int j = i; j < NG * NN; j += stride) ((int*)d_deg)[j] = 0;
    for (int j = i; j < NG * DD; j += stride) ((float*)d_gsum)[j] = 0.0f;
}

__global__ void hist_kernel(const int* __restrict__ e1,
                            const int* __restrict__ e2,
                            const int* __restrict__ e3) {
    int g = blockIdx.y;
    const int* ei = (g == 0) ? e1 : ((g == 1) ? e2 : e3);
    const int4* dst4 = (const int4*)(ei + NE);
    int stride = gridDim.x * blockDim.x;
    for (int i = blockIdx.x * blockDim.x + threadIdx.x; i < NE / 4; i += stride) {
        int4 d = dst4[i];
        atomicAdd(&d_deg[g][d.x], 1);
        atomicAdd(&d_deg[g][d.y], 1);
        atomicAdd(&d_deg[g][d.z], 1);
        atomicAdd(&d_deg[g][d.w], 1);
    }
}

__global__ void scan_pass1() {
    int g = blockIdx.y;
    int t = threadIdx.x;
    int base = blockIdx.x * 4096 + t * 16;
    int s = 0;
    #pragma unroll
    for (int i = 0; i < 16; i++) {
        int idx = base + i;
        if (idx < NN) s += d_deg[g][idx];
    }
    #pragma unroll
    for (int o = 16; o; o >>= 1) s += __shfl_down_sync(0xffffffffu, s, o);
    __shared__ int ws[8];
    if ((t & 31) == 0) ws[t >> 5] = s;
    __syncthreads();
    if (t == 0) {
        int v = 0;
        #pragma unroll
        for (int w = 0; w < 8; w++) v += ws[w];
        d_bsum[g][blockIdx.x] = v;
    }
}

__global__ void scan_pass2() {
    int t = threadIdx.x;
    int g = t >> 5, l = t & 31;
    int v = (l < NSCAN) ? d_bsum[g][l] : 0;
    int incl = v;
    #pragma unroll
    for (int o = 1; o < 32; o <<= 1) {
        int y = __shfl_up_sync(0xffffffffu, incl, o);
        if (l >= o) incl += y;
    }
    if (l < NSCAN) d_bsum[g][l] = incl - v;
    if (l == 0) d_start[g][NN] = NE;
}

__global__ void scan_pass3() {
    int g = blockIdx.y;
    int t = threadIdx.x;
    int base = blockIdx.x * 4096 + t * 16;
    int v[16];
    int s = 0;
    #pragma unroll
    for (int i = 0; i < 16; i++) {
        int idx = base + i;
        v[i] = (idx < NN) ? d_deg[g][idx] : 0;
        s += v[i];
    }
    int incl = s;
    #pragma unroll
    for (int o = 1; o < 32; o <<= 1) {
        int y = __shfl_up_sync(0xffffffffu, incl, o);
        if ((t & 31) >= o) incl += y;
    }
    __shared__ int ws[8];
    if ((t & 31) == 31) ws[t >> 5] = incl;
    __syncthreads();
    if (t == 0) {
        int run = 0;
        #pragma unroll
        for (int w = 0; w < 8; w++) { int tmp = ws[w]; ws[w] = run; run += tmp; }
    }
    __syncthreads();
    int run = d_bsum[g][blockIdx.x] + ws[t >> 5] + (incl - s);
    #pragma unroll
    for (int i = 0; i < 16; i++) {
        int idx = base + i;
        if (idx < NN) {
            d_start[g][idx]  = run;
            d_cursor[g][idx] = run;
            d_dinv[g][idx]   = rsqrtf((float)(v[i] + 1));
            run += v[i];
        }
    }
}

__global__ void fill_kernel(const int* __restrict__ e1,
                            const int* __restrict__ e2,
                            const int* __restrict__ e3) {
    int g = blockIdx.y;
    const int* ei = (g == 0) ? e1 : ((g == 1) ? e2 : e3);
    const int4* src4 = (const int4*)ei;
    const int4* dst4 = (const int4*)(ei + NE);
    int stride = gridDim.x * blockDim.x;
    int* srcs = d_srcs[g];
    int* cur  = d_cursor[g];
    for (int i = blockIdx.x * blockDim.x + threadIdx.x; i < NE / 4; i += stride) {
        int4 sv = src4[i];
        int4 dv = dst4[i];
        srcs[atomicAdd(&cur[dv.x], 1)] = sv.x;
        srcs[atomicAdd(&cur[dv.y], 1)] = sv.y;
        srcs[atomicAdd(&cur[dv.z], 1)] = sv.z;
        srcs[atomicAdd(&cur[dv.w], 1)] = sv.w;
    }
}

// ---------------- convert: y[n][d] = fp16(dinv[n] * x[n][d]) ------------------
__global__ void convert_kernel(const float* __restrict__ x1,
                               const float* __restrict__ x2,
                               const float* __restrict__ x3) {
    int g = blockIdx.y;
    const float4* x4 = (const float4*)((g == 0) ? x1 : ((g == 1) ? x2 : x3));
    const float* dinv = d_dinv[g];
    uint2* y2 = (uint2*)d_y[g];
    int stride = gridDim.x * blockDim.x;
    for (int i = blockIdx.x * blockDim.x + threadIdx.x; i < NN * 32; i += stride) {
        int n = i >> 5;
        float di = dinv[n];
        float4 v = x4[i];
        __half2 h0 = __floats2half2_rn(di * v.x, di * v.y);
        __half2 h1 = __floats2half2_rn(di * v.z, di * v.w);
        uint2 o;
        o.x = *(unsigned*)&h0;
        o.y = *(unsigned*)&h1;
        y2[i] = o;
    }
}

// ---------------- gather (fp16 reads, fp32 accum) -----------------------------
// z[dst] = dinv[dst] * ( sum_{src} y[src] + y[dst] )
__global__ void gather_kernel() {
    int g = blockIdx.y;
    const __half* y = d_y[g];
    int warp = (blockIdx.x * blockDim.x + threadIdx.x) >> 5;
    int lane = threadIdx.x & 31;
    if (warp >= NN) return;
    int n = warp;
    int s = d_start[g][n];
    int e = d_start[g][n + 1];
    const int* srcs = d_srcs[g];
    float2 a01 = make_float2(0.f, 0.f);
    float2 a23 = make_float2(0.f, 0.f);
    int i = s;
    for (; i + 4 <= e; i += 4) {
        int s0 = srcs[i], s1 = srcs[i + 1], s2 = srcs[i + 2], s3 = srcs[i + 3];
        uint2 v0 = *(const uint2*)(y + s0 * DD + lane * 4);
        uint2 v1 = *(const uint2*)(y + s1 * DD + lane * 4);
        uint2 v2 = *(const uint2*)(y + s2 * DD + lane * 4);
        uint2 v3 = *(const uint2*)(y + s3 * DD + lane * 4);
        float2 f;
        f = __half22float2(*(__half2*)&v0.x); a01.x += f.x; a01.y += f.y;
        f = __half22float2(*(__half2*)&v0.y); a23.x += f.x; a23.y += f.y;
        f = __half22float2(*(__half2*)&v1.x); a01.x += f.x; a01.y += f.y;
        f = __half22float2(*(__half2*)&v1.y); a23.x += f.x; a23.y += f.y;
        f = __half22float2(*(__half2*)&v2.x); a01.x += f.x; a01.y += f.y;
        f = __half22float2(*(__half2*)&v2.y); a23.x += f.x; a23.y += f.y;
        f = __half22float2(*(__half2*)&v3.x); a01.x += f.x; a01.y += f.y;
        f = __half22float2(*(__half2*)&v3.y); a23.x += f.x; a23.y += f.y;
    }
    for (; i < e; i++) {
        int s0 = srcs[i];
        uint2 v0 = *(const uint2*)(y + s0 * DD + lane * 4);
        float2 f;
        f = __half22float2(*(__half2*)&v0.x); a01.x += f.x; a01.y += f.y;
        f = __half22float2(*(__half2*)&v0.y); a23.x += f.x; a23.y += f.y;
    }
    // self contribution
    {
        uint2 v0 = *(const uint2*)(y + n * DD + lane * 4);
        float2 f;
        f = __half22float2(*(__half2*)&v0.x); a01.x += f.x; a01.y += f.y;
        f = __half22float2(*(__half2*)&v0.y); a23.x += f.x; a23.y += f.y;
    }
    float di = d_dinv[g][n];
    float4 r = make_float4(di * a01.x, di * a01.y, di * a23.x, di * a23.y);
    ((float4*)d_z[g])[n * 32 + lane] = r;
}

// ---------------- persistent GEMM: relu(z@W + b) column-summed ----------------
// block: 256 thr; tile 64 rows x 128 cols; warp 16x64; thread 4 rows x 8 cols
// smem: Ws[128][WP] (W transposed: Ws[col][k]), zs[64][ZP], bias, red
#define SM_WS 0
#define SM_ZS (DD * WP)
#define SM_BS (SM_ZS + 64 * ZP)
#define SM_RED (SM_BS + DD)
#define SM_TOT (SM_RED + DD)

__global__ void __launch_bounds__(256, 2)
gemm_kernel(const float* __restrict__ W1, const float* __restrict__ b1,
            const float* __restrict__ W2, const float* __restrict__ b2,
            const float* __restrict__ W3, const float* __restrict__ b3) {
    extern __shared__ float sm[];
    float* Ws = sm + SM_WS;
    float* zs = sm + SM_ZS;
    float* bs = sm + SM_BS;
    float* red = sm + SM_RED;

    int g = blockIdx.y;
    const float* W = (g == 0) ? W1 : ((g == 1) ? W2 : W3);
    const float* b = (g == 0) ? b1 : ((g == 1) ? b2 : b3);

    int t = threadIdx.x;
    int lane = t & 31, w = t >> 5;
    int a = lane & 3, bb = lane >> 2;          // a: 4 row slots, bb: 8 col slots
    int wr = (w & 3) * 16, wc = (w >> 2) * 64; // warp offsets

    // Ws[col][k] = W[k][col]
    for (int idx = t; idx < DD * DD; idx += 256) {
        int col = idx & 127, k = idx >> 7;
        Ws[col * WP + k] = W[idx];
    }
    if (t < DD) { bs[t] = b[t]; red[t] = 0.f; }
    __syncthreads();

    const float4* z4 = (const float4*)d_z[g];
    float colsum[8] = {0.f, 0.f, 0.f, 0.f, 0.f, 0.f, 0.f, 0.f};

    for (int tile = blockIdx.x; tile < NTILES; tile += GEMM_BLOCKS) {
        int row0 = tile * 64;
        // load z tile
        for (int i = t; i < 64 * 32; i += 256) {
            int r = i >> 5, c = i & 31;
            float4 v = (row0 + r < NN) ? z4[(row0 + r) * 32 + c]
                                       : make_float4(0.f, 0.f, 0.f, 0.f);
            *(float4*)(zs + r * ZP + c * 4) = v;
        }
        __syncthreads();

        ull acc[4][8];
        #pragma unroll
        for (int i = 0; i < 4; i++)
            #pragma unroll
            for (int j = 0; j < 8; j++) acc[i][j] = 0ull;

        #pragma unroll 4
        for (int k = 0; k < DD; k += 2) {
            ull zv[4], wv[8];
            #pragma unroll
            for (int i = 0; i < 4; i++)
                zv[i] = *(const ull*)(zs + (wr + a + 4 * i) * ZP + k);
            #pragma unroll
            for (int j = 0; j < 8; j++)
                wv[j] = *(const ull*)(Ws + (wc + bb + 8 * j) * WP + k);
            #pragma unroll
            for (int i = 0; i < 4; i++)
                #pragma unroll
                for (int j = 0; j < 8; j++)
                    acc[i][j] = ffma2(zv[i], wv[j], acc[i][j]);
        }

        // epilogue: +bias, relu, accumulate column sums over valid rows
        #pragma unroll
        for (int i = 0; i < 4; i++) {
            int row = row0 + wr + a + 4 * i;
            if (row < NN) {
                #pragma unroll
                for (int j = 0; j < 8; j++) {
                    float lo, hi;
                    unpack64(acc[i][j], lo, hi);
                    colsum[j] += fmaxf(lo + hi + bs[wc + bb + 8 * j], 0.f);
                }
            }
        }
        __syncthreads();
    }

    #pragma unroll
    for (int j = 0; j < 8; j++)
        atomicAdd(&red[wc + bb + 8 * j], colsum[j]);
    __syncthreads();
    if (t < DD) atomicAdd(&d_gsum[g][t], red[t]);
}

// ---------------- head --------------------------------------------------------
__global__ void finalize_kernel(const float* __restrict__ a1w, const float* __restrict__ a1b,
                                const float* __restrict__ a2w, const float* __restrict__ a2b,
                                const float* __restrict__ a3w, const float* __restrict__ a3b,
                                const float* __restrict__ f1w, const float* __restrict__ f1b,
                                const float* __restrict__ f2w, const float* __restrict__ f2b,
                                float* __restrict__ out) {
    __shared__ float xin[3 * DD];
    __shared__ float h1[DD];
    __shared__ float h2[DD];
    __shared__ float aw[4];
    __shared__ float xa[DD];
    int t = threadIdx.x;
    xin[t]          = d_gsum[0][t];
    xin[DD + t]     = d_gsum[1][t];
    xin[2 * DD + t] = d_gsum[2][t];
    __syncthreads();
    {
        float s = a1b[t];
        for (int j = 0; j < 3 * DD; j++) s += xin[j] * a1w[t * (3 * DD) + j];
        h1[t] = fmaxf(s, 0.f);
    }
    __syncthreads();
    {
        float s = a2b[t];
        for (int j = 0; j < DD; j++) s += h1[j] * a2w[t * DD + j];
        h2[t] = s;
    }
    __syncthreads();
    if (t < 3) {
        float s = a3b[t];
        for (int j = 0; j < DD; j++) s += fmaxf(h2[j], 0.f) * a3w[t * DD + j];
        aw[t] = s;
    }
    __syncthreads();
    if (t == 0) {
        float m = fmaxf(aw[0], fmaxf(aw[1], aw[2]));
        float e0 = expf(aw[0] - m), e1 = expf(aw[1] - m), e2 = expf(aw[2] - m);
        float S = e0 + e1 + e2;
        aw[0] = e0 / S; aw[1] = e1 / S; aw[2] = e2 / S;
    }
    __syncthreads();
    xa[t] = aw[0] * xin[t] + aw[1] * xin[DD + t] + aw[2] * xin[2 * DD + t];
    __syncthreads();
    float sg = f1b[t], sb = f2b[t];
    for (int j = 0; j < DD; j++) {
        float v = xa[j];
        sg += v * f1w[t * DD + j];
        sb += v * f2w[t * DD + j];
    }
    out[t]      = tanhf(sg);
    out[DD + t] = tanhf(sb);
}

// ---------------- launch ------------------------------------------------------
extern "C" void kernel_launch(void* const* d_in, const int* in_sizes, int n_in,
                              void* d_out, int out_size) {
    const float* x1 = (const float*)d_in[0];
    const float* x2 = (const float*)d_in[1];
    const float* x3 = (const float*)d_in[2];
    const int* e1 = (const int*)d_in[3];
    const int* e2 = (const int*)d_in[4];
    const int* e3 = (const int*)d_in[5];
    const float* W1 = (const float*)d_in[6];  const float* b1 = (const float*)d_in[7];
    const float* W2 = (const float*)d_in[8];  const float* b2 = (const float*)d_in[9];
    const float* W3 = (const float*)d_in[10]; const float* b3 = (const float*)d_in[11];
    const float* a1w = (const float*)d_in[12]; const float* a1b = (const float*)d_in[13];
    const float* a2w = (const float*)d_in[14]; const float* a2b = (const float*)d_in[15];
    const float* a3w = (const float*)d_in[16]; const float* a3b = (const float*)d_in[17];
    const float* f1w = (const float*)d_in[18]; const float* f1b = (const float*)d_in[19];
    const float* f2w = (const float*)d_in[20]; const float* f2b = (const float*)d_in[21];
    float* out = (float*)d_out;

    static bool attr_set = false;
    if (!attr_set) {
        cudaFuncSetAttribute(gemm_kernel, cudaFuncAttributeMaxDynamicSharedMemorySize,
                             SM_TOT * 4);
        attr_set = true;
    }

    zero_kernel<<<128, 256>>>();
    hist_kernel<<<dim3(256, NG), 256>>>(e1, e2, e3);
    scan_pass1<<<dim3(NSCAN, NG), 256>>>();
    scan_pass2<<<1, 96>>>();
    scan_pass3<<<dim3(NSCAN, NG), 256>>>();
    fill_kernel<<<dim3(256, NG), 256>>>(e1, e2, e3);
    convert_kernel<<<dim3(512, NG), 256>>>(x1, x2, x3);
    gather_kernel<<<dim3((NN + 7) / 8, NG), 256>>>();
    gemm_kernel<<<dim3(GEMM_BLOCKS, NG), 256, SM_TOT * 4>>>(W1, b1, W2, b2, W3, b3);
    finalize_kernel<<<1, DD>>>(a1w, a1b, a2w, a2b, a3w, a3b, f1w, f1b, f2w, f2b, out);
}

// round 5
// speedup vs baseline: 1.9867x; 1.9867x over previous
#include <cuda_runtime.h>
#include <cuda_fp16.h>
#include <math.h>

#define NN 50000
#define NE 800000
#define DD 128
#define NG 3
#define NSCAN 13
#define NT128 ((NN + 127) / 128)   // 391
#define ZPH 136                    // padded row pitch in halves

// ---------------- scratch ----------------------------------------------------
__device__ int    d_deg[NG][NN];
__device__ int    d_start[NG][NN + 1];
__device__ int    d_cursor[NG][NN];
__device__ int    d_srcs[NG][NE];
__device__ float  d_dinv[NG][NN];
__device__ __half d_y[NG][NN * DD];     // fp16 dinv[n]*x[n]
__device__ __half d_z[NG][NN * DD];     // aggregated features (fp16)
__device__ __half d_wt[NG][DD * DD];    // W transposed fp16: wt[j*128+k] = W[k][j]
__device__ float  d_gsum[NG][DD];
__device__ int    d_bsum[NG][16];

// ---------------- prep kernels -----------------------------------------------
__global__ void zero_kernel() {
    int i = blockIdx.x * blockDim.x + threadIdx.x;
    int stride = gridDim.x * blockDim.x;
    for (int j = i; j < NG * NN; j += stride) ((int*)d_deg)[j] = 0;
    for (int j = i; j < NG * DD; j += stride) ((float*)d_gsum)[j] = 0.0f;
    if (i < NG) d_start[i][NN] = NE;
}

__global__ void hist_kernel(const int* __restrict__ e1,
                            const int* __restrict__ e2,
                            const int* __restrict__ e3) {
    int g = blockIdx.y;
    const int* ei = (g == 0) ? e1 : ((g == 1) ? e2 : e3);
    const int4* dst4 = (const int4*)(ei + NE);
    int stride = gridDim.x * blockDim.x;
    for (int i = blockIdx.x * blockDim.x + threadIdx.x; i < NE / 4; i += stride) {
        int4 d = dst4[i];
        atomicAdd(&d_deg[g][d.x], 1);
        atomicAdd(&d_deg[g][d.y], 1);
        atomicAdd(&d_deg[g][d.z], 1);
        atomicAdd(&d_deg[g][d.w], 1);
    }
}

__global__ void scan_pass1() {   // grid (NSCAN, NG) x 256: block sums
    int g = blockIdx.y;
    int t = threadIdx.x;
    int base = blockIdx.x * 4096 + t * 16;
    int s = 0;
    #pragma unroll
    for (int i = 0; i < 16; i++) {
        int idx = base + i;
        if (idx < NN) s += d_deg[g][idx];
    }
    #pragma unroll
    for (int o = 16; o; o >>= 1) s += __shfl_down_sync(0xffffffffu, s, o);
    __shared__ int ws[8];
    if ((t & 31) == 0) ws[t >> 5] = s;
    __syncthreads();
    if (t == 0) {
        int v = 0;
        #pragma unroll
        for (int w = 0; w < 8; w++) v += ws[w];
        d_bsum[g][blockIdx.x] = v;
    }
}

__global__ void scan_pass3() {   // grid (NSCAN, NG) x 256; self-computes block offset
    int g = blockIdx.y;
    int t = threadIdx.x;
    __shared__ int bofs;
    if (t == 0) {
        int run = 0;
        for (int i = 0; i < (int)blockIdx.x; i++) run += d_bsum[g][i];
        bofs = run;
    }
    int base = blockIdx.x * 4096 + t * 16;
    int v[16];
    int s = 0;
    #pragma unroll
    for (int i = 0; i < 16; i++) {
        int idx = base + i;
        v[i] = (idx < NN) ? d_deg[g][idx] : 0;
        s += v[i];
    }
    int incl = s;
    #pragma unroll
    for (int o = 1; o < 32; o <<= 1) {
        int y = __shfl_up_sync(0xffffffffu, incl, o);
        if ((t & 31) >= o) incl += y;
    }
    __shared__ int ws[8];
    if ((t & 31) == 31) ws[t >> 5] = incl;
    __syncthreads();
    if (t == 0) {
        int run = 0;
        #pragma unroll
        for (int w = 0; w < 8; w++) { int tmp = ws[w]; ws[w] = run; run += tmp; }
    }
    __syncthreads();
    int run = bofs + ws[t >> 5] + (incl - s);
    #pragma unroll
    for (int i = 0; i < 16; i++) {
        int idx = base + i;
        if (idx < NN) {
            d_start[g][idx]  = run;
            d_cursor[g][idx] = run;
            d_dinv[g][idx]   = rsqrtf((float)(v[i] + 1));
            run += v[i];
        }
    }
}

__global__ void fill_kernel(const int* __restrict__ e1,
                            const int* __restrict__ e2,
                            const int* __restrict__ e3) {
    int g = blockIdx.y;
    const int* ei = (g == 0) ? e1 : ((g == 1) ? e2 : e3);
    const int4* src4 = (const int4*)ei;
    const int4* dst4 = (const int4*)(ei + NE);
    int stride = gridDim.x * blockDim.x;
    int* srcs = d_srcs[g];
    int* cur  = d_cursor[g];
    for (int i = blockIdx.x * blockDim.x + threadIdx.x; i < NE / 4; i += stride) {
        int4 sv = src4[i];
        int4 dv = dst4[i];
        srcs[atomicAdd(&cur[dv.x], 1)] = sv.x;
        srcs[atomicAdd(&cur[dv.y], 1)] = sv.y;
        srcs[atomicAdd(&cur[dv.z], 1)] = sv.z;
        srcs[atomicAdd(&cur[dv.w], 1)] = sv.w;
    }
}

// convert: y = fp16(dinv[n]*x[n]); last 4 blocks per graph transpose+convert W
__global__ void convert_kernel(const float* __restrict__ x1,
                               const float* __restrict__ x2,
                               const float* __restrict__ x3,
                               const float* __restrict__ W1,
                               const float* __restrict__ W2,
                               const float* __restrict__ W3) {
    int g = blockIdx.y;
    int t = threadIdx.x;
    if (blockIdx.x >= 512) {
        const float* W = (g == 0) ? W1 : ((g == 1) ? W2 : W3);
        __half* wt = d_wt[g];
        int gid = (blockIdx.x - 512) * 256 + t;   // 0..1023
        int j = gid >> 3;
        int k0 = (gid & 7) * 16;
        #pragma unroll
        for (int kk = 0; kk < 16; kk++)
            wt[j * DD + k0 + kk] = __float2half(W[(k0 + kk) * DD + j]);
        return;
    }
    const float4* x4 = (const float4*)((g == 0) ? x1 : ((g == 1) ? x2 : x3));
    const float* dinv = d_dinv[g];
    uint2* y2 = (uint2*)d_y[g];
    int stride = 512 * 256;
    for (int i = blockIdx.x * blockDim.x + t; i < NN * 32; i += stride) {
        int n = i >> 5;
        float di = dinv[n];
        float4 v = x4[i];
        __half2 h0 = __floats2half2_rn(di * v.x, di * v.y);
        __half2 h1 = __floats2half2_rn(di * v.z, di * v.w);
        uint2 o;
        o.x = *(unsigned*)&h0;
        o.y = *(unsigned*)&h1;
        y2[i] = o;
    }
}

// gather: z[dst] = fp16( dinv[dst] * ( sum_src y[src] + y[dst] ) )
__global__ void gather_kernel() {
    int g = blockIdx.y;
    const __half* y = d_y[g];
    int warp = (blockIdx.x * blockDim.x + threadIdx.x) >> 5;
    int lane = threadIdx.x & 31;
    if (warp >= NN) return;
    int n = warp;
    int s = d_start[g][n];
    int e = d_start[g][n + 1];
    const int* srcs = d_srcs[g];
    float2 a01 = make_float2(0.f, 0.f);
    float2 a23 = make_float2(0.f, 0.f);
    int i = s;
    for (; i + 4 <= e; i += 4) {
        int s0 = srcs[i], s1 = srcs[i + 1], s2 = srcs[i + 2], s3 = srcs[i + 3];
        uint2 v0 = *(const uint2*)(y + s0 * DD + lane * 4);
        uint2 v1 = *(const uint2*)(y + s1 * DD + lane * 4);
        uint2 v2 = *(const uint2*)(y + s2 * DD + lane * 4);
        uint2 v3 = *(const uint2*)(y + s3 * DD + lane * 4);
        float2 f;
        f = __half22float2(*(__half2*)&v0.x); a01.x += f.x; a01.y += f.y;
        f = __half22float2(*(__half2*)&v0.y); a23.x += f.x; a23.y += f.y;
        f = __half22float2(*(__half2*)&v1.x); a01.x += f.x; a01.y += f.y;
        f = __half22float2(*(__half2*)&v1.y); a23.x += f.x; a23.y += f.y;
        f = __half22float2(*(__half2*)&v2.x); a01.x += f.x; a01.y += f.y;
        f = __half22float2(*(__half2*)&v2.y); a23.x += f.x; a23.y += f.y;
        f = __half22float2(*(__half2*)&v3.x); a01.x += f.x; a01.y += f.y;
        f = __half22float2(*(__half2*)&v3.y); a23.x += f.x; a23.y += f.y;
    }
    for (; i < e; i++) {
        int s0 = srcs[i];
        uint2 v0 = *(const uint2*)(y + s0 * DD + lane * 4);
        float2 f;
        f = __half22float2(*(__half2*)&v0.x); a01.x += f.x; a01.y += f.y;
        f = __half22float2(*(__half2*)&v0.y); a23.x += f.x; a23.y += f.y;
    }
    {   // self
        uint2 v0 = *(const uint2*)(y + n * DD + lane * 4);
        float2 f;
        f = __half22float2(*(__half2*)&v0.x); a01.x += f.x; a01.y += f.y;
        f = __half22float2(*(__half2*)&v0.y); a23.x += f.x; a23.y += f.y;
    }
    float di = d_dinv[g][n];
    __half2 h0 = __floats2half2_rn(di * a01.x, di * a01.y);
    __half2 h1 = __floats2half2_rn(di * a23.x, di * a23.y);
    uint2 o;
    o.x = *(unsigned*)&h0;
    o.y = *(unsigned*)&h1;
    *(uint2*)(d_z[g] + n * DD + lane * 4) = o;
}

// ---------------- tensor-core GEMM: relu(z@W + b) column-summed ---------------
// grid (NT128, NG), 256 thr (8 warps). Tile 128 rows x 128 cols.
// warp w: rows [w*16, w*16+16), all 128 cols. mma m16n8k16 f32.f16.f16.f32.
#define SMB_ZS 0
#define SMB_WT (DD * ZPH * 2)                 // 34816
#define SMB_BS (SMB_WT + DD * ZPH * 2)        // 69632
#define SMB_RED (SMB_BS + DD * 4)             // 70144
#define SMB_TOT (SMB_RED + DD * 4)            // 70656

__global__ void __launch_bounds__(256, 2)
gemm_kernel(const float* __restrict__ b1, const float* __restrict__ b2,
            const float* __restrict__ b3) {
    extern __shared__ __align__(16) char smraw[];
    __half* zs = (__half*)(smraw + SMB_ZS);
    __half* Wt = (__half*)(smraw + SMB_WT);
    float*  bs = (float*)(smraw + SMB_BS);
    float*  red = (float*)(smraw + SMB_RED);

    int g = blockIdx.y;
    const float* b = (g == 0) ? b1 : ((g == 1) ? b2 : b3);
    int t = threadIdx.x;
    int row0 = blockIdx.x * 128;

    // load W tile (fp16, pre-transposed: Wt[j][k])
    const uint4* wsrc = (const uint4*)d_wt[g];
    for (int i = t; i < 2048; i += 256) {
        int r = i >> 4, c = i & 15;
        *(uint4*)&Wt[r * ZPH + c * 8] = wsrc[r * 16 + c];
    }
    // load z tile
    const uint4* zsrc = (const uint4*)d_z[g];
    uint4 zz; zz.x = zz.y = zz.z = zz.w = 0u;
    for (int i = t; i < 2048; i += 256) {
        int r = i >> 4, c = i & 15;
        int row = row0 + r;
        uint4 v = (row < NN) ? zsrc[row * 16 + c] : zz;
        *(uint4*)&zs[r * ZPH + c * 8] = v;
    }
    if (t < DD) { bs[t] = b[t]; red[t] = 0.f; }
    __syncthreads();

    int lane = t & 31, w = t >> 5;
    int qr = lane >> 2;          // 0..7
    int q2 = (lane & 3) * 2;     // 0,2,4,6

    const __half* ar0 = &zs[(w * 16 + qr) * ZPH + q2];
    const __half* ar8 = ar0 + 8 * ZPH;

    float acc[16][4];
    #pragma unroll
    for (int j = 0; j < 16; j++)
        #pragma unroll
        for (int c = 0; c < 4; c++) acc[j][c] = 0.f;

    #pragma unroll
    for (int kc = 0; kc < 8; kc++) {
        int k = kc * 16;
        unsigned a0 = *(const unsigned*)(ar0 + k);
        unsigned a1 = *(const unsigned*)(ar8 + k);
        unsigned a2 = *(const unsigned*)(ar0 + k + 8);
        unsigned a3 = *(const unsigned*)(ar8 + k + 8);
        #pragma unroll
        for (int j = 0; j < 16; j++) {
            const __half* bp = &Wt[(j * 8 + qr) * ZPH + q2 + k];
            unsigned bf0 = *(const unsigned*)bp;
            unsigned bf1 = *(const unsigned*)(bp + 8);
            asm volatile(
                "mma.sync.aligned.m16n8k16.row.col.f32.f16.f16.f32 "
                "{%0,%1,%2,%3}, {%4,%5,%6,%7}, {%8,%9}, {%0,%1,%2,%3};"
                : "+f"(acc[j][0]), "+f"(acc[j][1]), "+f"(acc[j][2]), "+f"(acc[j][3])
                : "r"(a0), "r"(a1), "r"(a2), "r"(a3), "r"(bf0), "r"(bf1));
        }
    }

    // epilogue: +bias, relu, sum over valid rows, reduce lanes (same col), smem atomics
    int r0 = row0 + w * 16 + qr;
    int r8 = r0 + 8;
    bool v0 = r0 < NN, v8 = r8 < NN;
    #pragma unroll
    for (int j = 0; j < 16; j++) {
        int c0 = j * 8 + q2;
        float bb0 = bs[c0], bb1 = bs[c0 + 1];
        float s0 = (v0 ? fmaxf(acc[j][0] + bb0, 0.f) : 0.f)
                 + (v8 ? fmaxf(acc[j][2] + bb0, 0.f) : 0.f);
        float s1 = (v0 ? fmaxf(acc[j][1] + bb1, 0.f) : 0.f)
                 + (v8 ? fmaxf(acc[j][3] + bb1, 0.f) : 0.f);
        s0 += __shfl_down_sync(0xffffffffu, s0, 16);
        s1 += __shfl_down_sync(0xffffffffu, s1, 16);
        s0 += __shfl_down_sync(0xffffffffu, s0, 8);
        s1 += __shfl_down_sync(0xffffffffu, s1, 8);
        s0 += __shfl_down_sync(0xffffffffu, s0, 4);
        s1 += __shfl_down_sync(0xffffffffu, s1, 4);
        if (lane < 4) {
            atomicAdd(&red[c0], s0);
            atomicAdd(&red[c0 + 1], s1);
        }
    }
    __syncthreads();
    if (t < DD) atomicAdd(&d_gsum[g][t], red[t]);
}

// ---------------- head --------------------------------------------------------
__global__ void finalize_kernel(const float* __restrict__ a1w, const float* __restrict__ a1b,
                                const float* __restrict__ a2w, const float* __restrict__ a2b,
                                const float* __restrict__ a3w, const float* __restrict__ a3b,
                                const float* __restrict__ f1w, const float* __restrict__ f1b,
                                const float* __restrict__ f2w, const float* __restrict__ f2b,
                                float* __restrict__ out) {
    __shared__ float xin[3 * DD];
    __shared__ float h1[DD];
    __shared__ float h2[DD];
    __shared__ float aw[4];
    __shared__ float xa[DD];
    int t = threadIdx.x;
    xin[t]          = d_gsum[0][t];
    xin[DD + t]     = d_gsum[1][t];
    xin[2 * DD + t] = d_gsum[2][t];
    __syncthreads();
    {
        float s = a1b[t];
        for (int j = 0; j < 3 * DD; j++) s += xin[j] * a1w[t * (3 * DD) + j];
        h1[t] = fmaxf(s, 0.f);
    }
    __syncthreads();
    {
        float s = a2b[t];
        for (int j = 0; j < DD; j++) s += h1[j] * a2w[t * DD + j];
        h2[t] = s;
    }
    __syncthreads();
    if (t < 3) {
        float s = a3b[t];
        for (int j = 0; j < DD; j++) s += fmaxf(h2[j], 0.f) * a3w[t * DD + j];
        aw[t] = s;
    }
    __syncthreads();
    if (t == 0) {
        float m = fmaxf(aw[0], fmaxf(aw[1], aw[2]));
        float e0 = expf(aw[0] - m), e1 = expf(aw[1] - m), e2 = expf(aw[2] - m);
        float S = e0 + e1 + e2;
        aw[0] = e0 / S; aw[1] = e1 / S; aw[2] = e2 / S;
    }
    __syncthreads();
    xa[t] = aw[0] * xin[t] + aw[1] * xin[DD + t] + aw[2] * xin[2 * DD + t];
    __syncthreads();
    float sg = f1b[t], sb = f2b[t];
    for (int j = 0; j < DD; j++) {
        float v = xa[j];
        sg += v * f1w[t * DD + j];
        sb += v * f2w[t * DD + j];
    }
    out[t]      = tanhf(sg);
    out[DD + t] = tanhf(sb);
}

// ---------------- launch ------------------------------------------------------
extern "C" void kernel_launch(void* const* d_in, const int* in_sizes, int n_in,
                              void* d_out, int out_size) {
    const float* x1 = (const float*)d_in[0];
    const float* x2 = (const float*)d_in[1];
    const float* x3 = (const float*)d_in[2];
    const int* e1 = (const int*)d_in[3];
    const int* e2 = (const int*)d_in[4];
    const int* e3 = (const int*)d_in[5];
    const float* W1 = (const float*)d_in[6];  const float* b1 = (const float*)d_in[7];
    const float* W2 = (const float*)d_in[8];  const float* b2 = (const float*)d_in[9];
    const float* W3 = (const float*)d_in[10]; const float* b3 = (const float*)d_in[11];
    const float* a1w = (const float*)d_in[12]; const float* a1b = (const float*)d_in[13];
    const float* a2w = (const float*)d_in[14]; const float* a2b = (const float*)d_in[15];
    const float* a3w = (const float*)d_in[16]; const float* a3b = (const float*)d_in[17];
    const float* f1w = (const float*)d_in[18]; const float* f1b = (const float*)d_in[19];
    const float* f2w = (const float*)d_in[20]; const float* f2b = (const float*)d_in[21];
    float* out = (float*)d_out;

    static bool attr_set = false;
    if (!attr_set) {
        cudaFuncSetAttribute(gemm_kernel, cudaFuncAttributeMaxDynamicSharedMemorySize,
                             SMB_TOT);
        attr_set = true;
    }

    zero_kernel<<<128, 256>>>();
    hist_kernel<<<dim3(256, NG), 256>>>(e1, e2, e3);
    scan_pass1<<<dim3(NSCAN, NG), 256>>>();
    scan_pass3<<<dim3(NSCAN, NG), 256>>>();
    fill_kernel<<<dim3(256, NG), 256>>>(e1, e2, e3);
    convert_kernel<<<dim3(516, NG), 256>>>(x1, x2, x3, W1, W2, W3);
    gather_kernel<<<dim3((NN + 7) / 8, NG), 256>>>();
    gemm_kernel<<<dim3(NT128, NG), 256, SMB_TOT>>>(b1, b2, b3);
    finalize_kernel<<<1, DD>>>(a1w, a1b, a2w, a2b, a3w, a3b, f1w, f1b, f2w, f2b, out);
}

// round 6
// speedup vs baseline: 2.0083x; 1.0109x over previous
#include <cuda_runtime.h>
#include <cuda_fp16.h>
#include <math.h>

#define NN 50000
#define NE 800000
#define DD 128
#define NG 3
#define NSCAN 13
#define NT128 ((NN + 127) / 128)   // 391
#define ZPH 136                    // padded row pitch in halves

// ---------------- scratch ----------------------------------------------------
__device__ int    d_deg[NG][NN];
__device__ int    d_start[NG][NN + 1];
__device__ int    d_cursor[NG][NN];
__device__ int    d_srcs[NG][NE];
__device__ float  d_dinv[NG][NN];
__device__ __half d_y[NG][NN * DD];     // fp16 dinv[n]*x[n]
__device__ __half d_z[NG][NN * DD];     // aggregated features (fp16)
__device__ __half d_wt[NG][DD * DD];    // W transposed fp16: wt[j*128+k] = W[k][j]
__device__ float  d_gsum[NG][DD];
__device__ int    d_bsum[NG][16];

// ---------------- prep kernels -----------------------------------------------
__global__ void zero_kernel() {
    int i = blockIdx.x * blockDim.x + threadIdx.x;
    int stride = gridDim.x * blockDim.x;
    for (int j = i; j < NG * NN; j += stride) ((int*)d_deg)[j] = 0;
    for (int j = i; j < NG * DD; j += stride) ((float*)d_gsum)[j] = 0.0f;
    if (i < NG) d_start[i][NN] = NE;
}

__global__ void hist_kernel(const int* __restrict__ e1,
                            const int* __restrict__ e2,
                            const int* __restrict__ e3) {
    int g = blockIdx.y;
    const int* ei = (g == 0) ? e1 : ((g == 1) ? e2 : e3);
    const int4* dst4 = (const int4*)(ei + NE);
    int stride = gridDim.x * blockDim.x;
    for (int i = blockIdx.x * blockDim.x + threadIdx.x; i < NE / 4; i += stride) {
        int4 d = dst4[i];
        atomicAdd(&d_deg[g][d.x], 1);
        atomicAdd(&d_deg[g][d.y], 1);
        atomicAdd(&d_deg[g][d.z], 1);
        atomicAdd(&d_deg[g][d.w], 1);
    }
}

__global__ void scan_pass1() {   // grid (NSCAN, NG) x 256: block sums
    int g = blockIdx.y;
    int t = threadIdx.x;
    int base = blockIdx.x * 4096 + t * 16;
    int s = 0;
    #pragma unroll
    for (int i = 0; i < 16; i++) {
        int idx = base + i;
        if (idx < NN) s += d_deg[g][idx];
    }
    #pragma unroll
    for (int o = 16; o; o >>= 1) s += __shfl_down_sync(0xffffffffu, s, o);
    __shared__ int ws[8];
    if ((t & 31) == 0) ws[t >> 5] = s;
    __syncthreads();
    if (t == 0) {
        int v = 0;
        #pragma unroll
        for (int w = 0; w < 8; w++) v += ws[w];
        d_bsum[g][blockIdx.x] = v;
    }
}

__global__ void scan_pass3() {   // grid (NSCAN, NG) x 256; self-computes block offset
    int g = blockIdx.y;
    int t = threadIdx.x;
    __shared__ int bofs;
    if (t == 0) {
        int run = 0;
        for (int i = 0; i < (int)blockIdx.x; i++) run += d_bsum[g][i];
        bofs = run;
    }
    int base = blockIdx.x * 4096 + t * 16;
    int v[16];
    int s = 0;
    #pragma unroll
    for (int i = 0; i < 16; i++) {
        int idx = base + i;
        v[i] = (idx < NN) ? d_deg[g][idx] : 0;
        s += v[i];
    }
    int incl = s;
    #pragma unroll
    for (int o = 1; o < 32; o <<= 1) {
        int y = __shfl_up_sync(0xffffffffu, incl, o);
        if ((t & 31) >= o) incl += y;
    }
    __shared__ int ws[8];
    if ((t & 31) == 31) ws[t >> 5] = incl;
    __syncthreads();
    if (t == 0) {
        int run = 0;
        #pragma unroll
        for (int w = 0; w < 8; w++) { int tmp = ws[w]; ws[w] = run; run += tmp; }
    }
    __syncthreads();
    int run = bofs + ws[t >> 5] + (incl - s);
    #pragma unroll
    for (int i = 0; i < 16; i++) {
        int idx = base + i;
        if (idx < NN) {
            d_start[g][idx]  = run;
            d_cursor[g][idx] = run;
            d_dinv[g][idx]   = rsqrtf((float)(v[i] + 1));
            run += v[i];
        }
    }
}

__global__ void fill_kernel(const int* __restrict__ e1,
                            const int* __restrict__ e2,
                            const int* __restrict__ e3) {
    int g = blockIdx.y;
    const int* ei = (g == 0) ? e1 : ((g == 1) ? e2 : e3);
    const int4* src4 = (const int4*)ei;
    const int4* dst4 = (const int4*)(ei + NE);
    int stride = gridDim.x * blockDim.x;
    int* srcs = d_srcs[g];
    int* cur  = d_cursor[g];
    for (int i = blockIdx.x * blockDim.x + threadIdx.x; i < NE / 4; i += stride) {
        int4 sv = src4[i];
        int4 dv = dst4[i];
        srcs[atomicAdd(&cur[dv.x], 1)] = sv.x;
        srcs[atomicAdd(&cur[dv.y], 1)] = sv.y;
        srcs[atomicAdd(&cur[dv.z], 1)] = sv.z;
        srcs[atomicAdd(&cur[dv.w], 1)] = sv.w;
    }
}

// convert: y = fp16(dinv[n]*x[n]); last 4 blocks per graph transpose+convert W
__global__ void convert_kernel(const float* __restrict__ x1,
                               const float* __restrict__ x2,
                               const float* __restrict__ x3,
                               const float* __restrict__ W1,
                               const float* __restrict__ W2,
                               const float* __restrict__ W3) {
    int g = blockIdx.y;
    int t = threadIdx.x;
    if (blockIdx.x >= 512) {
        const float* W = (g == 0) ? W1 : ((g == 1) ? W2 : W3);
        __half* wt = d_wt[g];
        int gid = (blockIdx.x - 512) * 256 + t;   // 0..1023
        int j = gid >> 3;
        int k0 = (gid & 7) * 16;
        #pragma unroll
        for (int kk = 0; kk < 16; kk++)
            wt[j * DD + k0 + kk] = __float2half(W[(k0 + kk) * DD + j]);
        return;
    }
    const float4* x4 = (const float4*)((g == 0) ? x1 : ((g == 1) ? x2 : x3));
    const float* dinv = d_dinv[g];
    uint2* y2 = (uint2*)d_y[g];
    int stride = 512 * 256;
    for (int i = blockIdx.x * blockDim.x + t; i < NN * 32; i += stride) {
        int n = i >> 5;
        float di = dinv[n];
        float4 v = x4[i];
        __half2 h0 = __floats2half2_rn(di * v.x, di * v.y);
        __half2 h1 = __floats2half2_rn(di * v.z, di * v.w);
        uint2 o;
        o.x = *(unsigned*)&h0;
        o.y = *(unsigned*)&h1;
        y2[i] = o;
    }
}

// gather: z[dst] = fp16( dinv[dst] * ( sum_src y[src] + y[dst] ) )
// one warp per node; 16 lanes per row (uint4 = 8 halves), 2 edges per iteration
__global__ void gather_kernel() {
    int g = blockIdx.y;
    const __half* y = d_y[g];
    int warp = (blockIdx.x * blockDim.x + threadIdx.x) >> 5;
    int lane = threadIdx.x & 31;
    if (warp >= NN) return;
    int n = warp;
    int ep  = lane >> 4;        // edge parity 0/1
    int off = lane & 15;        // 16B chunk within row
    int s = d_start[g][n];
    int e = d_start[g][n + 1];
    const int* srcs = d_srcs[g];

    float2 a0 = make_float2(0.f, 0.f);
    float2 a1 = make_float2(0.f, 0.f);
    float2 a2 = make_float2(0.f, 0.f);
    float2 a3 = make_float2(0.f, 0.f);

#define ACC8(vv) {                                              \
        const __half2* hh = (const __half2*)&(vv);              \
        float2 f;                                               \
        f = __half22float2(hh[0]); a0.x += f.x; a0.y += f.y;    \
        f = __half22float2(hh[1]); a1.x += f.x; a1.y += f.y;    \
        f = __half22float2(hh[2]); a2.x += f.x; a2.y += f.y;    \
        f = __half22float2(hh[3]); a3.x += f.x; a3.y += f.y;    }

    int i = s;
    // 8 edges per iteration (4 pairs)
    for (; i + 8 <= e; i += 8) {
        int s0 = srcs[i     + ep];
        int s1 = srcs[i + 2 + ep];
        int s2 = srcs[i + 4 + ep];
        int s3 = srcs[i + 6 + ep];
        uint4 v0 = *(const uint4*)(y + s0 * DD + off * 8);
        uint4 v1 = *(const uint4*)(y + s1 * DD + off * 8);
        uint4 v2 = *(const uint4*)(y + s2 * DD + off * 8);
        uint4 v3 = *(const uint4*)(y + s3 * DD + off * 8);
        ACC8(v0); ACC8(v1); ACC8(v2); ACC8(v3);
    }
    // remaining pairs
    for (; i + 2 <= e; i += 2) {
        int s0 = srcs[i + ep];
        uint4 v0 = *(const uint4*)(y + s0 * DD + off * 8);
        ACC8(v0);
    }
    // odd tail edge -> parity-0 half-warp; self row -> parity-1 half-warp
    if (ep == 0) {
        if (i < e) {
            int s0 = srcs[i];
            uint4 v0 = *(const uint4*)(y + s0 * DD + off * 8);
            ACC8(v0);
        }
    } else {
        uint4 v0 = *(const uint4*)(y + n * DD + off * 8);
        ACC8(v0);
    }
#undef ACC8

    // merge the two edge-parity partials: lane l += lane l+16
    a0.x += __shfl_down_sync(0xffffffffu, a0.x, 16);
    a0.y += __shfl_down_sync(0xffffffffu, a0.y, 16);
    a1.x += __shfl_down_sync(0xffffffffu, a1.x, 16);
    a1.y += __shfl_down_sync(0xffffffffu, a1.y, 16);
    a2.x += __shfl_down_sync(0xffffffffu, a2.x, 16);
    a2.y += __shfl_down_sync(0xffffffffu, a2.y, 16);
    a3.x += __shfl_down_sync(0xffffffffu, a3.x, 16);
    a3.y += __shfl_down_sync(0xffffffffu, a3.y, 16);

    if (ep == 0) {
        float di = d_dinv[g][n];
        __half2 h0 = __floats2half2_rn(di * a0.x, di * a0.y);
        __half2 h1 = __floats2half2_rn(di * a1.x, di * a1.y);
        __half2 h2 = __floats2half2_rn(di * a2.x, di * a2.y);
        __half2 h3 = __floats2half2_rn(di * a3.x, di * a3.y);
        uint4 o;
        o.x = *(unsigned*)&h0;
        o.y = *(unsigned*)&h1;
        o.z = *(unsigned*)&h2;
        o.w = *(unsigned*)&h3;
        *(uint4*)(d_z[g] + n * DD + off * 8) = o;
    }
}

// ---------------- tensor-core GEMM: relu(z@W + b) column-summed ---------------
// grid (NT128, NG), 256 thr (8 warps). Tile 128 rows x 128 cols.
// warp w: rows [w*16, w*16+16), all 128 cols. mma m16n8k16 f32.f16.f16.f32.
#define SMB_ZS 0
#define SMB_WT (DD * ZPH * 2)                 // 34816
#define SMB_BS (SMB_WT + DD * ZPH * 2)        // 69632
#define SMB_RED (SMB_BS + DD * 4)             // 70144
#define SMB_TOT (SMB_RED + DD * 4)            // 70656

__global__ void __launch_bounds__(256, 2)
gemm_kernel(const float* __restrict__ b1, const float* __restrict__ b2,
            const float* __restrict__ b3) {
    extern __shared__ __align__(16) char smraw[];
    __half* zs = (__half*)(smraw + SMB_ZS);
    __half* Wt = (__half*)(smraw + SMB_WT);
    float*  bs = (float*)(smraw + SMB_BS);
    float*  red = (float*)(smraw + SMB_RED);

    int g = blockIdx.y;
    const float* b = (g == 0) ? b1 : ((g == 1) ? b2 : b3);
    int t = threadIdx.x;
    int row0 = blockIdx.x * 128;

    // load W tile (fp16, pre-transposed: Wt[j][k])
    const uint4* wsrc = (const uint4*)d_wt[g];
    for (int i = t; i < 2048; i += 256) {
        int r = i >> 4, c = i & 15;
        *(uint4*)&Wt[r * ZPH + c * 8] = wsrc[r * 16 + c];
    }
    // load z tile
    const uint4* zsrc = (const uint4*)d_z[g];
    uint4 zz; zz.x = zz.y = zz.z = zz.w = 0u;
    for (int i = t; i < 2048; i += 256) {
        int r = i >> 4, c = i & 15;
        int row = row0 + r;
        uint4 v = (row < NN) ? zsrc[row * 16 + c] : zz;
        *(uint4*)&zs[r * ZPH + c * 8] = v;
    }
    if (t < DD) { bs[t] = b[t]; red[t] = 0.f; }
    __syncthreads();

    int lane = t & 31, w = t >> 5;
    int qr = lane >> 2;          // 0..7
    int q2 = (lane & 3) * 2;     // 0,2,4,6

    const __half* ar0 = &zs[(w * 16 + qr) * ZPH + q2];
    const __half* ar8 = ar0 + 8 * ZPH;

    float acc[16][4];
    #pragma unroll
    for (int j = 0; j < 16; j++)
        #pragma unroll
        for (int c = 0; c < 4; c++) acc[j][c] = 0.f;

    #pragma unroll
    for (int kc = 0; kc < 8; kc++) {
        int k = kc * 16;
        unsigned a0 = *(const unsigned*)(ar0 + k);
        unsigned a1 = *(const unsigned*)(ar8 + k);
        unsigned a2 = *(const unsigned*)(ar0 + k + 8);
        unsigned a3 = *(const unsigned*)(ar8 + k + 8);
        #pragma unroll
        for (int j = 0; j < 16; j++) {
            const __half* bp = &Wt[(j * 8 + qr) * ZPH + q2 + k];
            unsigned bf0 = *(const unsigned*)bp;
            unsigned bf1 = *(const unsigned*)(bp + 8);
            asm volatile(
                "mma.sync.aligned.m16n8k16.row.col.f32.f16.f16.f32 "
                "{%0,%1,%2,%3}, {%4,%5,%6,%7}, {%8,%9}, {%0,%1,%2,%3};"
                : "+f"(acc[j][0]), "+f"(acc[j][1]), "+f"(acc[j][2]), "+f"(acc[j][3])
                : "r"(a0), "r"(a1), "r"(a2), "r"(a3), "r"(bf0), "r"(bf1));
        }
    }

    // epilogue: +bias, relu, sum over valid rows, reduce lanes (same col), smem atomics
    int r0 = row0 + w * 16 + qr;
    int r8 = r0 + 8;
    bool v0 = r0 < NN, v8 = r8 < NN;
    #pragma unroll
    for (int j = 0; j < 16; j++) {
        int c0 = j * 8 + q2;
        float bb0 = bs[c0], bb1 = bs[c0 + 1];
        float s0 = (v0 ? fmaxf(acc[j][0] + bb0, 0.f) : 0.f)
                 + (v8 ? fmaxf(acc[j][2] + bb0, 0.f) : 0.f);
        float s1 = (v0 ? fmaxf(acc[j][1] + bb1, 0.f) : 0.f)
                 + (v8 ? fmaxf(acc[j][3] + bb1, 0.f) : 0.f);
        s0 += __shfl_down_sync(0xffffffffu, s0, 16);
        s1 += __shfl_down_sync(0xffffffffu, s1, 16);
        s0 += __shfl_down_sync(0xffffffffu, s0, 8);
        s1 += __shfl_down_sync(0xffffffffu, s1, 8);
        s0 += __shfl_down_sync(0xffffffffu, s0, 4);
        s1 += __shfl_down_sync(0xffffffffu, s1, 4);
        if (lane < 4) {
            atomicAdd(&red[c0], s0);
            atomicAdd(&red[c0 + 1], s1);
        }
    }
    __syncthreads();
    if (t < DD) atomicAdd(&d_gsum[g][t], red[t]);
}

// ---------------- head --------------------------------------------------------
__global__ void finalize_kernel(const float* __restrict__ a1w, const float* __restrict__ a1b,
                                const float* __restrict__ a2w, const float* __restrict__ a2b,
                                const float* __restrict__ a3w, const float* __restrict__ a3b,
                                const float* __restrict__ f1w, const float* __restrict__ f1b,
                                const float* __restrict__ f2w, const float* __restrict__ f2b,
                                float* __restrict__ out) {
    __shared__ float xin[3 * DD];
    __shared__ float h1[DD];
    __shared__ float h2[DD];
    __shared__ float aw[4];
    __shared__ float xa[DD];
    int t = threadIdx.x;
    xin[t]          = d_gsum[0][t];
    xin[DD + t]     = d_gsum[1][t];
    xin[2 * DD + t] = d_gsum[2][t];
    __syncthreads();
    {
        float s = a1b[t];
        for (int j = 0; j < 3 * DD; j++) s += xin[j] * a1w[t * (3 * DD) + j];
        h1[t] = fmaxf(s, 0.f);
    }
    __syncthreads();
    {
        float s = a2b[t];
        for (int j = 0; j < DD; j++) s += h1[j] * a2w[t * DD + j];
        h2[t] = s;
    }
    __syncthreads();
    if (t < 3) {
        float s = a3b[t];
        for (int j = 0; j < DD; j++) s += fmaxf(h2[j], 0.f) * a3w[t * DD + j];
        aw[t] = s;
    }
    __syncthreads();
    if (t == 0) {
        float m = fmaxf(aw[0], fmaxf(aw[1], aw[2]));
        float e0 = expf(aw[0] - m), e1 = expf(aw[1] - m), e2 = expf(aw[2] - m);
        float S = e0 + e1 + e2;
        aw[0] = e0 / S; aw[1] = e1 / S; aw[2] = e2 / S;
    }
    __syncthreads();
    xa[t] = aw[0] * xin[t] + aw[1] * xin[DD + t] + aw[2] * xin[2 * DD + t];
    __syncthreads();
    float sg = f1b[t], sb = f2b[t];
    for (int j = 0; j < DD; j++) {
        float v = xa[j];
        sg += v * f1w[t * DD + j];
        sb += v * f2w[t * DD + j];
    }
    out[t]      = tanhf(sg);
    out[DD + t] = tanhf(sb);
}

// ---------------- launch ------------------------------------------------------
extern "C" void kernel_launch(void* const* d_in, const int* in_sizes, int n_in,
                              void* d_out, int out_size) {
    const float* x1 = (const float*)d_in[0];
    const float* x2 = (const float*)d_in[1];
    const float* x3 = (const float*)d_in[2];
    const int* e1 = (const int*)d_in[3];
    const int* e2 = (const int*)d_in[4];
    const int* e3 = (const int*)d_in[5];
    const float* W1 = (const float*)d_in[6];  const float* b1 = (const float*)d_in[7];
    const float* W2 = (const float*)d_in[8];  const float* b2 = (const float*)d_in[9];
    const float* W3 = (const float*)d_in[10]; const float* b3 = (const float*)d_in[11];
    const float* a1w = (const float*)d_in[12]; const float* a1b = (const float*)d_in[13];
    const float* a2w = (const float*)d_in[14]; const float* a2b = (const float*)d_in[15];
    const float* a3w = (const float*)d_in[16]; const float* a3b = (const float*)d_in[17];
    const float* f1w = (const float*)d_in[18]; const float* f1b = (const float*)d_in[19];
    const float* f2w = (const float*)d_in[20]; const float* f2b = (const float*)d_in[21];
    float* out = (float*)d_out;

    static bool attr_set = false;
    if (!attr_set) {
        cudaFuncSetAttribute(gemm_kernel, cudaFuncAttributeMaxDynamicSharedMemorySize,
                             SMB_TOT);
        attr_set = true;
    }

    zero_kernel<<<128, 256>>>();
    hist_kernel<<<dim3(256, NG), 256>>>(e1, e2, e3);
    scan_pass1<<<dim3(NSCAN, NG), 256>>>();
    scan_pass3<<<dim3(NSCAN, NG), 256>>>();
    fill_kernel<<<dim3(256, NG), 256>>>(e1, e2, e3);
    convert_kernel<<<dim3(516, NG), 256>>>(x1, x2, x3, W1, W2, W3);
    gather_kernel<<<dim3((NN + 7) / 8, NG), 256>>>();
    gemm_kernel<<<dim3(NT128, NG), 256, SMB_TOT>>>(b1, b2, b3);
    finalize_kernel<<<1, DD>>>(a1w, a1b, a2w, a2b, a3w, a3b, f1w, f1b, f2w, f2b, out);
}

// round 7
// speedup vs baseline: 2.0579x; 1.0247x over previous
#include <cuda_runtime.h>
#include <cuda_fp16.h>
#include <math.h>

#define NN 50000
#define NE 800000
#define DD 128
#define NG 3
#define NSCAN 13
#define NT128 ((NN + 127) / 128)   // 391
#define ZPH 136                    // padded row pitch in halves

// ---------------- scratch ----------------------------------------------------
__device__ int    d_deg[NG][NN];
__device__ int    d_start[NG][NN + 1];
__device__ int    d_cursor[NG][NN];
__device__ int    d_srcs[NG][NE];
__device__ float  d_dinv[NG][NN];
__device__ __half d_y[NG][NN * DD];     // fp16 dinv[n]*x[n]
__device__ __half d_z[NG][NN * DD];     // aggregated features (fp16)
__device__ __half d_wt[NG][DD * DD];    // W transposed fp16: wt[j*128+k] = W[k][j]
__device__ float  d_gsum[NG][DD];
__device__ int    d_bsum[NG][16];

// ---------------- prep kernels -----------------------------------------------
__global__ void zero_kernel() {
    int i = blockIdx.x * blockDim.x + threadIdx.x;
    int stride = gridDim.x * blockDim.x;
    for (int j = i; j < NG * NN; j += stride) ((int*)d_deg)[j] = 0;
    for (int j = i; j < NG * DD; j += stride) ((float*)d_gsum)[j] = 0.0f;
    if (i < NG) d_start[i][NN] = NE;
}

__global__ void hist_kernel(const int* __restrict__ e1,
                            const int* __restrict__ e2,
                            const int* __restrict__ e3) {
    int g = blockIdx.y;
    const int* ei = (g == 0) ? e1 : ((g == 1) ? e2 : e3);
    const int4* dst4 = (const int4*)(ei + NE);
    int stride = gridDim.x * blockDim.x;
    for (int i = blockIdx.x * blockDim.x + threadIdx.x; i < NE / 4; i += stride) {
        int4 d = dst4[i];
        atomicAdd(&d_deg[g][d.x], 1);
        atomicAdd(&d_deg[g][d.y], 1);
        atomicAdd(&d_deg[g][d.z], 1);
        atomicAdd(&d_deg[g][d.w], 1);
    }
}

__global__ void scan_pass1() {   // grid (NSCAN, NG) x 256: block sums
    int g = blockIdx.y;
    int t = threadIdx.x;
    int base = blockIdx.x * 4096 + t * 16;
    int s = 0;
    #pragma unroll
    for (int i = 0; i < 16; i++) {
        int idx = base + i;
        if (idx < NN) s += d_deg[g][idx];
    }
    #pragma unroll
    for (int o = 16; o; o >>= 1) s += __shfl_down_sync(0xffffffffu, s, o);
    __shared__ int ws[8];
    if ((t & 31) == 0) ws[t >> 5] = s;
    __syncthreads();
    if (t == 0) {
        int v = 0;
        #pragma unroll
        for (int w = 0; w < 8; w++) v += ws[w];
        d_bsum[g][blockIdx.x] = v;
    }
}

__global__ void scan_pass3() {   // grid (NSCAN, NG) x 256; self-computes block offset
    int g = blockIdx.y;
    int t = threadIdx.x;
    __shared__ int bofs;
    if (t == 0) {
        int run = 0;
        for (int i = 0; i < (int)blockIdx.x; i++) run += d_bsum[g][i];
        bofs = run;
    }
    int base = blockIdx.x * 4096 + t * 16;
    int v[16];
    int s = 0;
    #pragma unroll
    for (int i = 0; i < 16; i++) {
        int idx = base + i;
        v[i] = (idx < NN) ? d_deg[g][idx] : 0;
        s += v[i];
    }
    int incl = s;
    #pragma unroll
    for (int o = 1; o < 32; o <<= 1) {
        int y = __shfl_up_sync(0xffffffffu, incl, o);
        if ((t & 31) >= o) incl += y;
    }
    __shared__ int ws[8];
    if ((t & 31) == 31) ws[t >> 5] = incl;
    __syncthreads();
    if (t == 0) {
        int run = 0;
        #pragma unroll
        for (int w = 0; w < 8; w++) { int tmp = ws[w]; ws[w] = run; run += tmp; }
    }
    __syncthreads();
    int run = bofs + ws[t >> 5] + (incl - s);
    #pragma unroll
    for (int i = 0; i < 16; i++) {
        int idx = base + i;
        if (idx < NN) {
            d_start[g][idx]  = run;
            d_cursor[g][idx] = run;
            d_dinv[g][idx]   = rsqrtf((float)(v[i] + 1));
            run += v[i];
        }
    }
}

__global__ void fill_kernel(const int* __restrict__ e1,
                            const int* __restrict__ e2,
                            const int* __restrict__ e3) {
    int g = blockIdx.y;
    const int* ei = (g == 0) ? e1 : ((g == 1) ? e2 : e3);
    const int4* src4 = (const int4*)ei;
    const int4* dst4 = (const int4*)(ei + NE);
    int stride = gridDim.x * blockDim.x;
    int* srcs = d_srcs[g];
    int* cur  = d_cursor[g];
    for (int i = blockIdx.x * blockDim.x + threadIdx.x; i < NE / 4; i += stride) {
        int4 sv = src4[i];
        int4 dv = dst4[i];
        srcs[atomicAdd(&cur[dv.x], 1)] = sv.x;
        srcs[atomicAdd(&cur[dv.y], 1)] = sv.y;
        srcs[atomicAdd(&cur[dv.z], 1)] = sv.z;
        srcs[atomicAdd(&cur[dv.w], 1)] = sv.w;
    }
}

// convert: y = fp16(dinv[n]*x[n]); last 4 blocks per graph transpose+convert W
__global__ void convert_kernel(const float* __restrict__ x1,
                               const float* __restrict__ x2,
                               const float* __restrict__ x3,
                               const float* __restrict__ W1,
                               const float* __restrict__ W2,
                               const float* __restrict__ W3) {
    int g = blockIdx.y;
    int t = threadIdx.x;
    if (blockIdx.x >= 512) {
        const float* W = (g == 0) ? W1 : ((g == 1) ? W2 : W3);
        __half* wt = d_wt[g];
        int gid = (blockIdx.x - 512) * 256 + t;   // 0..1023
        int j = gid >> 3;
        int k0 = (gid & 7) * 16;
        #pragma unroll
        for (int kk = 0; kk < 16; kk++)
            wt[j * DD + k0 + kk] = __float2half(W[(k0 + kk) * DD + j]);
        return;
    }
    const float4* x4 = (const float4*)((g == 0) ? x1 : ((g == 1) ? x2 : x3));
    const float* dinv = d_dinv[g];
    uint2* y2 = (uint2*)d_y[g];
    int stride = 512 * 256;
    for (int i = blockIdx.x * blockDim.x + t; i < NN * 32; i += stride) {
        int n = i >> 5;
        float di = dinv[n];
        float4 v = x4[i];
        __half2 h0 = __floats2half2_rn(di * v.x, di * v.y);
        __half2 h1 = __floats2half2_rn(di * v.z, di * v.w);
        uint2 o;
        o.x = *(unsigned*)&h0;
        o.y = *(unsigned*)&h1;
        y2[i] = o;
    }
}

// gather: z[dst] = fp16( dinv[dst] * ( sum_src y[src] + y[dst] ) )
// one warp per node; 16 lanes per row (uint4 = 8 halves), 2 edges per iteration.
// Accumulation in fp16 (HADD2) — ALU count per edge drops ~3x vs fp32 cvt+add.
__global__ void gather_kernel() {
    int g = blockIdx.y;
    const __half* y = d_y[g];
    int warp = (blockIdx.x * blockDim.x + threadIdx.x) >> 5;
    int lane = threadIdx.x & 31;
    if (warp >= NN) return;
    int n = warp;
    int ep  = lane >> 4;        // edge parity 0/1
    int off = lane & 15;        // 16B chunk within row
    int s = d_start[g][n];
    int e = d_start[g][n + 1];
    const int* srcs = d_srcs[g];

    __half2 zero2 = __float2half2_rn(0.f);
    __half2 a0 = zero2, a1 = zero2, a2 = zero2, a3 = zero2;

#define ACC8(vv) {                                    \
        const __half2* hh = (const __half2*)&(vv);    \
        a0 = __hadd2(a0, hh[0]);                      \
        a1 = __hadd2(a1, hh[1]);                      \
        a2 = __hadd2(a2, hh[2]);                      \
        a3 = __hadd2(a3, hh[3]);                      }

    int i = s;
    // 8 edges per iteration (4 pairs)
    for (; i + 8 <= e; i += 8) {
        int s0 = srcs[i     + ep];
        int s1 = srcs[i + 2 + ep];
        int s2 = srcs[i + 4 + ep];
        int s3 = srcs[i + 6 + ep];
        uint4 v0 = *(const uint4*)(y + s0 * DD + off * 8);
        uint4 v1 = *(const uint4*)(y + s1 * DD + off * 8);
        uint4 v2 = *(const uint4*)(y + s2 * DD + off * 8);
        uint4 v3 = *(const uint4*)(y + s3 * DD + off * 8);
        ACC8(v0); ACC8(v1); ACC8(v2); ACC8(v3);
    }
    // remaining pairs
    for (; i + 2 <= e; i += 2) {
        int s0 = srcs[i + ep];
        uint4 v0 = *(const uint4*)(y + s0 * DD + off * 8);
        ACC8(v0);
    }
    // odd tail edge -> parity-0 half-warp; self row -> parity-1 half-warp
    if (ep == 0) {
        if (i < e) {
            int s0 = srcs[i];
            uint4 v0 = *(const uint4*)(y + s0 * DD + off * 8);
            ACC8(v0);
        }
    } else {
        uint4 v0 = *(const uint4*)(y + n * DD + off * 8);
        ACC8(v0);
    }
#undef ACC8

    // merge the two edge-parity partials: lane l += lane l+16 (packed half2 shfl)
    {
        unsigned u0 = __shfl_down_sync(0xffffffffu, *(unsigned*)&a0, 16);
        unsigned u1 = __shfl_down_sync(0xffffffffu, *(unsigned*)&a1, 16);
        unsigned u2 = __shfl_down_sync(0xffffffffu, *(unsigned*)&a2, 16);
        unsigned u3 = __shfl_down_sync(0xffffffffu, *(unsigned*)&a3, 16);
        a0 = __hadd2(a0, *(__half2*)&u0);
        a1 = __hadd2(a1, *(__half2*)&u1);
        a2 = __hadd2(a2, *(__half2*)&u2);
        a3 = __hadd2(a3, *(__half2*)&u3);
    }

    if (ep == 0) {
        float di = d_dinv[g][n];
        float2 f0 = __half22float2(a0);
        float2 f1 = __half22float2(a1);
        float2 f2 = __half22float2(a2);
        float2 f3 = __half22float2(a3);
        __half2 h0 = __floats2half2_rn(di * f0.x, di * f0.y);
        __half2 h1 = __floats2half2_rn(di * f1.x, di * f1.y);
        __half2 h2 = __floats2half2_rn(di * f2.x, di * f2.y);
        __half2 h3 = __floats2half2_rn(di * f3.x, di * f3.y);
        uint4 o;
        o.x = *(unsigned*)&h0;
        o.y = *(unsigned*)&h1;
        o.z = *(unsigned*)&h2;
        o.w = *(unsigned*)&h3;
        *(uint4*)(d_z[g] + n * DD + off * 8) = o;
    }
}

// ---------------- tensor-core GEMM: relu(z@W + b) column-summed ---------------
// grid (NT128, NG), 256 thr (8 warps). Tile 128 rows x 128 cols.
// warp w: rows [w*16, w*16+16), all 128 cols. mma m16n8k16 f32.f16.f16.f32.
#define SMB_ZS 0
#define SMB_WT (DD * ZPH * 2)                 // 34816
#define SMB_BS (SMB_WT + DD * ZPH * 2)        // 69632
#define SMB_RED (SMB_BS + DD * 4)             // 70144
#define SMB_TOT (SMB_RED + DD * 4)            // 70656

__global__ void __launch_bounds__(256, 2)
gemm_kernel(const float* __restrict__ b1, const float* __restrict__ b2,
            const float* __restrict__ b3) {
    extern __shared__ __align__(16) char smraw[];
    __half* zs = (__half*)(smraw + SMB_ZS);
    __half* Wt = (__half*)(smraw + SMB_WT);
    float*  bs = (float*)(smraw + SMB_BS);
    float*  red = (float*)(smraw + SMB_RED);

    int g = blockIdx.y;
    const float* b = (g == 0) ? b1 : ((g == 1) ? b2 : b3);
    int t = threadIdx.x;
    int row0 = blockIdx.x * 128;

    // load W tile (fp16, pre-transposed: Wt[j][k])
    const uint4* wsrc = (const uint4*)d_wt[g];
    for (int i = t; i < 2048; i += 256) {
        int r = i >> 4, c = i & 15;
        *(uint4*)&Wt[r * ZPH + c * 8] = wsrc[r * 16 + c];
    }
    // load z tile
    const uint4* zsrc = (const uint4*)d_z[g];
    uint4 zz; zz.x = zz.y = zz.z = zz.w = 0u;
    for (int i = t; i < 2048; i += 256) {
        int r = i >> 4, c = i & 15;
        int row = row0 + r;
        uint4 v = (row < NN) ? zsrc[row * 16 + c] : zz;
        *(uint4*)&zs[r * ZPH + c * 8] = v;
    }
    if (t < DD) { bs[t] = b[t]; red[t] = 0.f; }
    __syncthreads();

    int lane = t & 31, w = t >> 5;
    int qr = lane >> 2;          // 0..7
    int q2 = (lane & 3) * 2;     // 0,2,4,6

    const __half* ar0 = &zs[(w * 16 + qr) * ZPH + q2];
    const __half* ar8 = ar0 + 8 * ZPH;

    float acc[16][4];
    #pragma unroll
    for (int j = 0; j < 16; j++)
        #pragma unroll
        for (int c = 0; c < 4; c++) acc[j][c] = 0.f;

    #pragma unroll
    for (int kc = 0; kc < 8; kc++) {
        int k = kc * 16;
        unsigned a0 = *(const unsigned*)(ar0 + k);
        unsigned a1 = *(const unsigned*)(ar8 + k);
        unsigned a2 = *(const unsigned*)(ar0 + k + 8);
        unsigned a3 = *(const unsigned*)(ar8 + k + 8);
        #pragma unroll
        for (int j = 0; j < 16; j++) {
            const __half* bp = &Wt[(j * 8 + qr) * ZPH + q2 + k];
            unsigned bf0 = *(const unsigned*)bp;
            unsigned bf1 = *(const unsigned*)(bp + 8);
            asm volatile(
                "mma.sync.aligned.m16n8k16.row.col.f32.f16.f16.f32 "
                "{%0,%1,%2,%3}, {%4,%5,%6,%7}, {%8,%9}, {%0,%1,%2,%3};"
                : "+f"(acc[j][0]), "+f"(acc[j][1]), "+f"(acc[j][2]), "+f"(acc[j][3])
                : "r"(a0), "r"(a1), "r"(a2), "r"(a3), "r"(bf0), "r"(bf1));
        }
    }

    // epilogue: +bias, relu, sum over valid rows, reduce lanes (same col), smem atomics
    int r0 = row0 + w * 16 + qr;
    int r8 = r0 + 8;
    bool v0 = r0 < NN, v8 = r8 < NN;
    #pragma unroll
    for (int j = 0; j < 16; j++) {
        int c0 = j * 8 + q2;
        float bb0 = bs[c0], bb1 = bs[c0 + 1];
        float s0 = (v0 ? fmaxf(acc[j][0] + bb0, 0.f) : 0.f)
                 + (v8 ? fmaxf(acc[j][2] + bb0, 0.f) : 0.f);
        float s1 = (v0 ? fmaxf(acc[j][1] + bb1, 0.f) : 0.f)
                 + (v8 ? fmaxf(acc[j][3] + bb1, 0.f) : 0.f);
        s0 += __shfl_down_sync(0xffffffffu, s0, 16);
        s1 += __shfl_down_sync(0xffffffffu, s1, 16);
        s0 += __shfl_down_sync(0xffffffffu, s0, 8);
        s1 += __shfl_down_sync(0xffffffffu, s1, 8);
        s0 += __shfl_down_sync(0xffffffffu, s0, 4);
        s1 += __shfl_down_sync(0xffffffffu, s1, 4);
        if (lane < 4) {
            atomicAdd(&red[c0], s0);
            atomicAdd(&red[c0 + 1], s1);
        }
    }
    __syncthreads();
    if (t < DD) atomicAdd(&d_gsum[g][t], red[t]);
}

// ---------------- head --------------------------------------------------------
__global__ void finalize_kernel(const float* __restrict__ a1w, const float* __restrict__ a1b,
                                const float* __restrict__ a2w, const float* __restrict__ a2b,
                                const float* __restrict__ a3w, const float* __restrict__ a3b,
                                const float* __restrict__ f1w, const float* __restrict__ f1b,
                                const float* __restrict__ f2w, const float* __restrict__ f2b,
                                float* __restrict__ out) {
    __shared__ float xin[3 * DD];
    __shared__ float h1[DD];
    __shared__ float h2[DD];
    __shared__ float aw[4];
    __shared__ float xa[DD];
    int t = threadIdx.x;
    xin[t]          = d_gsum[0][t];
    xin[DD + t]     = d_gsum[1][t];
    xin[2 * DD + t] = d_gsum[2][t];
    __syncthreads();
    {
        float s = a1b[t];
        for (int j = 0; j < 3 * DD; j++) s += xin[j] * a1w[t * (3 * DD) + j];
        h1[t] = fmaxf(s, 0.f);
    }
    __syncthreads();
    {
        float s = a2b[t];
        for (int j = 0; j < DD; j++) s += h1[j] * a2w[t * DD + j];
        h2[t] = s;
    }
    __syncthreads();
    if (t < 3) {
        float s = a3b[t];
        for (int j = 0; j < DD; j++) s += fmaxf(h2[j], 0.f) * a3w[t * DD + j];
        aw[t] = s;
    }
    __syncthreads();
    if (t == 0) {
        float m = fmaxf(aw[0], fmaxf(aw[1], aw[2]));
        float e0 = expf(aw[0] - m), e1 = expf(aw[1] - m), e2 = expf(aw[2] - m);
        float S = e0 + e1 + e2;
        aw[0] = e0 / S; aw[1] = e1 / S; aw[2] = e2 / S;
    }
    __syncthreads();
    xa[t] = aw[0] * xin[t] + aw[1] * xin[DD + t] + aw[2] * xin[2 * DD + t];
    __syncthreads();
    float sg = f1b[t], sb = f2b[t];
    for (int j = 0; j < DD; j++) {
        float v = xa[j];
        sg += v * f1w[t * DD + j];
        sb += v * f2w[t * DD + j];
    }
    out[t]      = tanhf(sg);
    out[DD + t] = tanhf(sb);
}

// ---------------- launch ------------------------------------------------------
extern "C" void kernel_launch(void* const* d_in, const int* in_sizes, int n_in,
                              void* d_out, int out_size) {
    const float* x1 = (const float*)d_in[0];
    const float* x2 = (const float*)d_in[1];
    const float* x3 = (const float*)d_in[2];
    const int* e1 = (const int*)d_in[3];
    const int* e2 = (const int*)d_in[4];
    const int* e3 = (const int*)d_in[5];
    const float* W1 = (const float*)d_in[6];  const float* b1 = (const float*)d_in[7];
    const float* W2 = (const float*)d_in[8];  const float* b2 = (const float*)d_in[9];
    const float* W3 = (const float*)d_in[10]; const float* b3 = (const float*)d_in[11];
    const float* a1w = (const float*)d_in[12]; const float* a1b = (const float*)d_in[13];
    const float* a2w = (const float*)d_in[14]; const float* a2b = (const float*)d_in[15];
    const float* a3w = (const float*)d_in[16]; const float* a3b = (const float*)d_in[17];
    const float* f1w = (const float*)d_in[18]; const float* f1b = (const float*)d_in[19];
    const float* f2w = (const float*)d_in[20]; const float* f2b = (const float*)d_in[21];
    float* out = (float*)d_out;

    static bool attr_set = false;
    if (!attr_set) {
        cudaFuncSetAttribute(gemm_kernel, cudaFuncAttributeMaxDynamicSharedMemorySize,
                             SMB_TOT);
        attr_set = true;
    }

    zero_kernel<<<128, 256>>>();
    hist_kernel<<<dim3(256, NG), 256>>>(e1, e2, e3);
    scan_pass1<<<dim3(NSCAN, NG), 256>>>();
    scan_pass3<<<dim3(NSCAN, NG), 256>>>();
    fill_kernel<<<dim3(256, NG), 256>>>(e1, e2, e3);
    convert_kernel<<<dim3(516, NG), 256>>>(x1, x2, x3, W1, W2, W3);
    gather_kernel<<<dim3((NN + 7) / 8, NG), 256>>>();
    gemm_kernel<<<dim3(NT128, NG), 256, SMB_TOT>>>(b1, b2, b3);
    finalize_kernel<<<1, DD>>>(a1w, a1b, a2w, a2b, a3w, a3b, f1w, f1b, f2w, f2b, out);
}

// round 8
// speedup vs baseline: 2.1640x; 1.0516x over previous
#include <cuda_runtime.h>
#include <cuda_fp16.h>
#include <math.h>

#define NN 50000
#define NE 800000
#define DD 128
#define NG 3
#define NSCAN 13
#define NT128 ((NN + 127) / 128)   // 391
#define ZPH 136                    // padded row pitch in halves

// ---------------- scratch ----------------------------------------------------
__device__ int           d_deg[NG][NN];
__device__ int           d_start[NG][NN + 1];
__device__ int           d_cursor[NG][NN];
__device__ int           d_srcs[NG][NE];
__device__ float         d_dinv[NG][NN];
__device__ unsigned char d_y8[NG][NN * DD];   // fp8 e4m3 of 64*dinv[n]*x[n]
__device__ __half        d_z[NG][NN * DD];    // aggregated features (fp16)
__device__ __half        d_wt[NG][DD * DD];   // W transposed fp16
__device__ float         d_gsum[NG][DD];
__device__ int           d_bsum[NG][16];

// ---------------- fp8 helpers -------------------------------------------------
// pack two f32 -> e4m3x2 (lo = first elem, hi = second elem)
__device__ __forceinline__ unsigned short f32x2_to_e4m3x2(float lo, float hi) {
    unsigned short r;
    asm("cvt.rn.satfinite.e4m3x2.f32 %0, %1, %2;" : "=h"(r) : "f"(hi), "f"(lo));
    return r;
}
// unpack e4m3x2 -> half2 (lo byte -> lo half)
__device__ __forceinline__ __half2 e4m3x2_to_h2(unsigned short u) {
    unsigned r;
    asm("cvt.rn.f16x2.e4m3x2 %0, %1;" : "=r"(r) : "h"(u));
    return *(__half2*)&r;
}

// ---------------- prep kernels -----------------------------------------------
__global__ void zero_kernel() {
    int i = blockIdx.x * blockDim.x + threadIdx.x;
    int stride = gridDim.x * blockDim.x;
    for (int j = i; j < NG * NN; j += stride) ((int*)d_deg)[j] = 0;
    for (int j = i; j < NG * DD; j += stride) ((float*)d_gsum)[j] = 0.0f;
    if (i < NG) d_start[i][NN] = NE;
}

__global__ void hist_kernel(const int* __restrict__ e1,
                            const int* __restrict__ e2,
                            const int* __restrict__ e3) {
    int g = blockIdx.y;
    const int* ei = (g == 0) ? e1 : ((g == 1) ? e2 : e3);
    const int4* dst4 = (const int4*)(ei + NE);
    int stride = gridDim.x * blockDim.x;
    for (int i = blockIdx.x * blockDim.x + threadIdx.x; i < NE / 4; i += stride) {
        int4 d = dst4[i];
        atomicAdd(&d_deg[g][d.x], 1);
        atomicAdd(&d_deg[g][d.y], 1);
        atomicAdd(&d_deg[g][d.z], 1);
        atomicAdd(&d_deg[g][d.w], 1);
    }
}

__global__ void scan_pass1() {   // grid (NSCAN, NG) x 256: block sums
    int g = blockIdx.y;
    int t = threadIdx.x;
    int base = blockIdx.x * 4096 + t * 16;
    int s = 0;
    #pragma unroll
    for (int i = 0; i < 16; i++) {
        int idx = base + i;
        if (idx < NN) s += d_deg[g][idx];
    }
    #pragma unroll
    for (int o = 16; o; o >>= 1) s += __shfl_down_sync(0xffffffffu, s, o);
    __shared__ int ws[8];
    if ((t & 31) == 0) ws[t >> 5] = s;
    __syncthreads();
    if (t == 0) {
        int v = 0;
        #pragma unroll
        for (int w = 0; w < 8; w++) v += ws[w];
        d_bsum[g][blockIdx.x] = v;
    }
}

__global__ void scan_pass3() {   // grid (NSCAN, NG) x 256; self-computes block offset
    int g = blockIdx.y;
    int t = threadIdx.x;
    __shared__ int bofs;
    if (t == 0) {
        int run = 0;
        for (int i = 0; i < (int)blockIdx.x; i++) run += d_bsum[g][i];
        bofs = run;
    }
    int base = blockIdx.x * 4096 + t * 16;
    int v[16];
    int s = 0;
    #pragma unroll
    for (int i = 0; i < 16; i++) {
        int idx = base + i;
        v[i] = (idx < NN) ? d_deg[g][idx] : 0;
        s += v[i];
    }
    int incl = s;
    #pragma unroll
    for (int o = 1; o < 32; o <<= 1) {
        int y = __shfl_up_sync(0xffffffffu, incl, o);
        if ((t & 31) >= o) incl += y;
    }
    __shared__ int ws[8];
    if ((t & 31) == 31) ws[t >> 5] = incl;
    __syncthreads();
    if (t == 0) {
        int run = 0;
        #pragma unroll
        for (int w = 0; w < 8; w++) { int tmp = ws[w]; ws[w] = run; run += tmp; }
    }
    __syncthreads();
    int run = bofs + ws[t >> 5] + (incl - s);
    #pragma unroll
    for (int i = 0; i < 16; i++) {
        int idx = base + i;
        if (idx < NN) {
            d_start[g][idx]  = run;
            d_cursor[g][idx] = run;
            d_dinv[g][idx]   = rsqrtf((float)(v[i] + 1));
            run += v[i];
        }
    }
}

__global__ void fill_kernel(const int* __restrict__ e1,
                            const int* __restrict__ e2,
                            const int* __restrict__ e3) {
    int g = blockIdx.y;
    const int* ei = (g == 0) ? e1 : ((g == 1) ? e2 : e3);
    const int4* src4 = (const int4*)ei;
    const int4* dst4 = (const int4*)(ei + NE);
    int stride = gridDim.x * blockDim.x;
    int* srcs = d_srcs[g];
    int* cur  = d_cursor[g];
    for (int i = blockIdx.x * blockDim.x + threadIdx.x; i < NE / 4; i += stride) {
        int4 sv = src4[i];
        int4 dv = dst4[i];
        srcs[atomicAdd(&cur[dv.x], 1)] = sv.x;
        srcs[atomicAdd(&cur[dv.y], 1)] = sv.y;
        srcs[atomicAdd(&cur[dv.z], 1)] = sv.z;
        srcs[atomicAdd(&cur[dv.w], 1)] = sv.w;
    }
}

// convert: y8 = e4m3(64*dinv[n]*x[n]); last 4 blocks per graph transpose+convert W
__global__ void convert_kernel(const float* __restrict__ x1,
                               const float* __restrict__ x2,
                               const float* __restrict__ x3,
                               const float* __restrict__ W1,
                               const float* __restrict__ W2,
                               const float* __restrict__ W3) {
    int g = blockIdx.y;
    int t = threadIdx.x;
    if (blockIdx.x >= 512) {
        const float* W = (g == 0) ? W1 : ((g == 1) ? W2 : W3);
        __half* wt = d_wt[g];
        int gid = (blockIdx.x - 512) * 256 + t;   // 0..1023
        int j = gid >> 3;
        int k0 = (gid & 7) * 16;
        #pragma unroll
        for (int kk = 0; kk < 16; kk++)
            wt[j * DD + k0 + kk] = __float2half(W[(k0 + kk) * DD + j]);
        return;
    }
    const float4* x4 = (const float4*)((g == 0) ? x1 : ((g == 1) ? x2 : x3));
    const float* dinv = d_dinv[g];
    uint4* y4 = (uint4*)d_y8[g];            // 16 fp8 per uint4; row = 8 uint4
    int stride = 512 * 256;
    for (int i = blockIdx.x * blockDim.x + t; i < NN * 8; i += stride) {
        int n = i >> 3;                     // node
        int c = i & 7;                      // 16-elem chunk
        float sc = 64.f * dinv[n];
        const float4* xp = x4 + n * 32 + c * 4;
        float4 v0 = xp[0], v1 = xp[1], v2 = xp[2], v3 = xp[3];
        unsigned short s0 = f32x2_to_e4m3x2(sc * v0.x, sc * v0.y);
        unsigned short s1 = f32x2_to_e4m3x2(sc * v0.z, sc * v0.w);
        unsigned short s2 = f32x2_to_e4m3x2(sc * v1.x, sc * v1.y);
        unsigned short s3 = f32x2_to_e4m3x2(sc * v1.z, sc * v1.w);
        unsigned short s4 = f32x2_to_e4m3x2(sc * v2.x, sc * v2.y);
        unsigned short s5 = f32x2_to_e4m3x2(sc * v2.z, sc * v2.w);
        unsigned short s6 = f32x2_to_e4m3x2(sc * v3.x, sc * v3.y);
        unsigned short s7 = f32x2_to_e4m3x2(sc * v3.z, sc * v3.w);
        uint4 o;
        o.x = (unsigned)s0 | ((unsigned)s1 << 16);
        o.y = (unsigned)s2 | ((unsigned)s3 << 16);
        o.z = (unsigned)s4 | ((unsigned)s5 << 16);
        o.w = (unsigned)s6 | ((unsigned)s7 << 16);
        y4[i] = o;
    }
}

// gather: z[dst] = fp16( (dinv[dst]/64) * ( sum_src y8[src] + y8[dst] ) )
// one warp per node; 8 lanes per 128B fp8 row (uint4 = 16 fp8), 4 edges/iter.
__global__ void gather_kernel() {
    int g = blockIdx.y;
    const uint4* ybase = (const uint4*)d_y8[g];   // row = 8 uint4
    int warp = (blockIdx.x * blockDim.x + threadIdx.x) >> 5;
    int lane = threadIdx.x & 31;
    if (warp >= NN) return;
    int n = warp;
    int ep  = lane >> 3;        // edge slot 0..3
    int off = lane & 7;         // 16B chunk within row
    int s = d_start[g][n];
    int e = d_start[g][n + 1];
    const int* srcs = d_srcs[g];

    __half2 zero2 = __float2half2_rn(0.f);
    __half2 a0 = zero2, a1 = zero2, a2 = zero2, a3 = zero2;
    __half2 a4 = zero2, a5 = zero2, a6 = zero2, a7 = zero2;

#define ACC16(vv) {                                                   \
        a0 = __hadd2(a0, e4m3x2_to_h2((unsigned short)((vv).x)));     \
        a1 = __hadd2(a1, e4m3x2_to_h2((unsigned short)((vv).x >> 16)));\
        a2 = __hadd2(a2, e4m3x2_to_h2((unsigned short)((vv).y)));     \
        a3 = __hadd2(a3, e4m3x2_to_h2((unsigned short)((vv).y >> 16)));\
        a4 = __hadd2(a4, e4m3x2_to_h2((unsigned short)((vv).z)));     \
        a5 = __hadd2(a5, e4m3x2_to_h2((unsigned short)((vv).z >> 16)));\
        a6 = __hadd2(a6, e4m3x2_to_h2((unsigned short)((vv).w)));     \
        a7 = __hadd2(a7, e4m3x2_to_h2((unsigned short)((vv).w >> 16)));}

    int i = s;
    for (; i + 8 <= e; i += 8) {       // 8 edges (2 groups of 4)
        int s0 = srcs[i + ep];
        int s1 = srcs[i + 4 + ep];
        uint4 v0 = ybase[s0 * 8 + off];
        uint4 v1 = ybase[s1 * 8 + off];
        ACC16(v0); ACC16(v1);
    }
    for (; i + 4 <= e; i += 4) {       // 4 edges
        int s0 = srcs[i + ep];
        uint4 v0 = ybase[s0 * 8 + off];
        ACC16(v0);
    }
    {   // tail: r in 0..3 edges for slots ep<r; slot ep==r adds self row
        int r = e - i;
        int sv = (ep < r) ? srcs[i + ep] : ((ep == r) ? n : -1);
        if (sv >= 0) {
            uint4 v0 = ybase[sv * 8 + off];
            ACC16(v0);
        }
    }
#undef ACC16

    // merge 4 edge-slot partials: +16 then +8
#define MRG(aa, d) {                                                     \
        unsigned uu = __shfl_down_sync(0xffffffffu, *(unsigned*)&(aa), d);\
        (aa) = __hadd2((aa), *(__half2*)&uu);                             }
    MRG(a0,16) MRG(a1,16) MRG(a2,16) MRG(a3,16)
    MRG(a4,16) MRG(a5,16) MRG(a6,16) MRG(a7,16)
    MRG(a0,8)  MRG(a1,8)  MRG(a2,8)  MRG(a3,8)
    MRG(a4,8)  MRG(a5,8)  MRG(a6,8)  MRG(a7,8)
#undef MRG

    if (ep == 0) {
        float di = d_dinv[g][n] * (1.f / 64.f);
        float2 f0 = __half22float2(a0);
        float2 f1 = __half22float2(a1);
        float2 f2 = __half22float2(a2);
        float2 f3 = __half22float2(a3);
        float2 f4 = __half22float2(a4);
        float2 f5 = __half22float2(a5);
        float2 f6 = __half22float2(a6);
        float2 f7 = __half22float2(a7);
        __half2 h0 = __floats2half2_rn(di * f0.x, di * f0.y);
        __half2 h1 = __floats2half2_rn(di * f1.x, di * f1.y);
        __half2 h2 = __floats2half2_rn(di * f2.x, di * f2.y);
        __half2 h3 = __floats2half2_rn(di * f3.x, di * f3.y);
        __half2 h4 = __floats2half2_rn(di * f4.x, di * f4.y);
        __half2 h5 = __floats2half2_rn(di * f5.x, di * f5.y);
        __half2 h6 = __floats2half2_rn(di * f6.x, di * f6.y);
        __half2 h7 = __floats2half2_rn(di * f7.x, di * f7.y);
        uint4 o0, o1;
        o0.x = *(unsigned*)&h0; o0.y = *(unsigned*)&h1;
        o0.z = *(unsigned*)&h2; o0.w = *(unsigned*)&h3;
        o1.x = *(unsigned*)&h4; o1.y = *(unsigned*)&h5;
        o1.z = *(unsigned*)&h6; o1.w = *(unsigned*)&h7;
        uint4* zp = (uint4*)(d_z[g] + n * DD + off * 16);
        zp[0] = o0;
        zp[1] = o1;
    }
}

// ---------------- tensor-core GEMM: relu(z@W + b) column-summed ---------------
#define SMB_ZS 0
#define SMB_WT (DD * ZPH * 2)                 // 34816
#define SMB_BS (SMB_WT + DD * ZPH * 2)        // 69632
#define SMB_RED (SMB_BS + DD * 4)             // 70144
#define SMB_TOT (SMB_RED + DD * 4)            // 70656

__global__ void __launch_bounds__(256, 2)
gemm_kernel(const float* __restrict__ b1, const float* __restrict__ b2,
            const float* __restrict__ b3) {
    extern __shared__ __align__(16) char smraw[];
    __half* zs = (__half*)(smraw + SMB_ZS);
    __half* Wt = (__half*)(smraw + SMB_WT);
    float*  bs = (float*)(smraw + SMB_BS);
    float*  red = (float*)(smraw + SMB_RED);

    int g = blockIdx.y;
    const float* b = (g == 0) ? b1 : ((g == 1) ? b2 : b3);
    int t = threadIdx.x;
    int row0 = blockIdx.x * 128;

    const uint4* wsrc = (const uint4*)d_wt[g];
    for (int i = t; i < 2048; i += 256) {
        int r = i >> 4, c = i & 15;
        *(uint4*)&Wt[r * ZPH + c * 8] = wsrc[r * 16 + c];
    }
    const uint4* zsrc = (const uint4*)d_z[g];
    uint4 zz; zz.x = zz.y = zz.z = zz.w = 0u;
    for (int i = t; i < 2048; i += 256) {
        int r = i >> 4, c = i & 15;
        int row = row0 + r;
        uint4 v = (row < NN) ? zsrc[row * 16 + c] : zz;
        *(uint4*)&zs[r * ZPH + c * 8] = v;
    }
    if (t < DD) { bs[t] = b[t]; red[t] = 0.f; }
    __syncthreads();

    int lane = t & 31, w = t >> 5;
    int qr = lane >> 2;
    int q2 = (lane & 3) * 2;

    const __half* ar0 = &zs[(w * 16 + qr) * ZPH + q2];
    const __half* ar8 = ar0 + 8 * ZPH;

    float acc[16][4];
    #pragma unroll
    for (int j = 0; j < 16; j++)
        #pragma unroll
        for (int c = 0; c < 4; c++) acc[j][c] = 0.f;

    #pragma unroll
    for (int kc = 0; kc < 8; kc++) {
        int k = kc * 16;
        unsigned a0 = *(const unsigned*)(ar0 + k);
        unsigned a1 = *(const unsigned*)(ar8 + k);
        unsigned a2 = *(const unsigned*)(ar0 + k + 8);
        unsigned a3 = *(const unsigned*)(ar8 + k + 8);
        #pragma unroll
        for (int j = 0; j < 16; j++) {
            const __half* bp = &Wt[(j * 8 + qr) * ZPH + q2 + k];
            unsigned bf0 = *(const unsigned*)bp;
            unsigned bf1 = *(const unsigned*)(bp + 8);
            asm volatile(
                "mma.sync.aligned.m16n8k16.row.col.f32.f16.f16.f32 "
                "{%0,%1,%2,%3}, {%4,%5,%6,%7}, {%8,%9}, {%0,%1,%2,%3};"
                : "+f"(acc[j][0]), "+f"(acc[j][1]), "+f"(acc[j][2]), "+f"(acc[j][3])
                : "r"(a0), "r"(a1), "r"(a2), "r"(a3), "r"(bf0), "r"(bf1));
        }
    }

    int r0 = row0 + w * 16 + qr;
    int r8 = r0 + 8;
    bool v0 = r0 < NN, v8 = r8 < NN;
    #pragma unroll
    for (int j = 0; j < 16; j++) {
        int c0 = j * 8 + q2;
        float bb0 = bs[c0], bb1 = bs[c0 + 1];
        float s0 = (v0 ? fmaxf(acc[j][0] + bb0, 0.f) : 0.f)
                 + (v8 ? fmaxf(acc[j][2] + bb0, 0.f) : 0.f);
        float s1 = (v0 ? fmaxf(acc[j][1] + bb1, 0.f) : 0.f)
                 + (v8 ? fmaxf(acc[j][3] + bb1, 0.f) : 0.f);
        s0 += __shfl_down_sync(0xffffffffu, s0, 16);
        s1 += __shfl_down_sync(0xffffffffu, s1, 16);
        s0 += __shfl_down_sync(0xffffffffu, s0, 8);
        s1 += __shfl_down_sync(0xffffffffu, s1, 8);
        s0 += __shfl_down_sync(0xffffffffu, s0, 4);
        s1 += __shfl_down_sync(0xffffffffu, s1, 4);
        if (lane < 4) {
            atomicAdd(&red[c0], s0);
            atomicAdd(&red[c0 + 1], s1);
        }
    }
    __syncthreads();
    if (t < DD) atomicAdd(&d_gsum[g][t], red[t]);
}

// ---------------- head --------------------------------------------------------
__global__ void finalize_kernel(const float* __restrict__ a1w, const float* __restrict__ a1b,
                                const float* __restrict__ a2w, const float* __restrict__ a2b,
                                const float* __restrict__ a3w, const float* __restrict__ a3b,
                                const float* __restrict__ f1w, const float* __restrict__ f1b,
                                const float* __restrict__ f2w, const float* __restrict__ f2b,
                                float* __restrict__ out) {
    __shared__ float xin[3 * DD];
    __shared__ float h1[DD];
    __shared__ float h2[DD];
    __shared__ float aw[4];
    __shared__ float xa[DD];
    int t = threadIdx.x;
    xin[t]          = d_gsum[0][t];
    xin[DD + t]     = d_gsum[1][t];
    xin[2 * DD + t] = d_gsum[2][t];
    __syncthreads();
    {
        float s = a1b[t];
        for (int j = 0; j < 3 * DD; j++) s += xin[j] * a1w[t * (3 * DD) + j];
        h1[t] = fmaxf(s, 0.f);
    }
    __syncthreads();
    {
        float s = a2b[t];
        for (int j = 0; j < DD; j++) s += h1[j] * a2w[t * DD + j];
        h2[t] = s;
    }
    __syncthreads();
    if (t < 3) {
        float s = a3b[t];
        for (int j = 0; j < DD; j++) s += fmaxf(h2[j], 0.f) * a3w[t * DD + j];
        aw[t] = s;
    }
    __syncthreads();
    if (t == 0) {
        float m = fmaxf(aw[0], fmaxf(aw[1], aw[2]));
        float e0 = expf(aw[0] - m), e1 = expf(aw[1] - m), e2 = expf(aw[2] - m);
        float S = e0 + e1 + e2;
        aw[0] = e0 / S; aw[1] = e1 / S; aw[2] = e2 / S;
    }
    __syncthreads();
    xa[t] = aw[0] * xin[t] + aw[1] * xin[DD + t] + aw[2] * xin[2 * DD + t];
    __syncthreads();
    float sg = f1b[t], sb = f2b[t];
    for (int j = 0; j < DD; j++) {
        float v = xa[j];
        sg += v * f1w[t * DD + j];
        sb += v * f2w[t * DD + j];
    }
    out[t]      = tanhf(sg);
    out[DD + t] = tanhf(sb);
}

// ---------------- launch ------------------------------------------------------
extern "C" void kernel_launch(void* const* d_in, const int* in_sizes, int n_in,
                              void* d_out, int out_size) {
    const float* x1 = (const float*)d_in[0];
    const float* x2 = (const float*)d_in[1];
    const float* x3 = (const float*)d_in[2];
    const int* e1 = (const int*)d_in[3];
    const int* e2 = (const int*)d_in[4];
    const int* e3 = (const int*)d_in[5];
    const float* W1 = (const float*)d_in[6];  const float* b1 = (const float*)d_in[7];
    const float* W2 = (const float*)d_in[8];  const float* b2 = (const float*)d_in[9];
    const float* W3 = (const float*)d_in[10]; const float* b3 = (const float*)d_in[11];
    const float* a1w = (const float*)d_in[12]; const float* a1b = (const float*)d_in[13];
    const float* a2w = (const float*)d_in[14]; const float* a2b = (const float*)d_in[15];
    const float* a3w = (const float*)d_in[16]; const float* a3b = (const float*)d_in[17];
    const float* f1w = (const float*)d_in[18]; const float* f1b = (const float*)d_in[19];
    const float* f2w = (const float*)d_in[20]; const float* f2b = (const float*)d_in[21];
    float* out = (float*)d_out;

    static bool attr_set = false;
    if (!attr_set) {
        cudaFuncSetAttribute(gemm_kernel, cudaFuncAttributeMaxDynamicSharedMemorySize,
                             SMB_TOT);
        attr_set = true;
    }

    zero_kernel<<<128, 256>>>();
    hist_kernel<<<dim3(256, NG), 256>>>(e1, e2, e3);
    scan_pass1<<<dim3(NSCAN, NG), 256>>>();
    scan_pass3<<<dim3(NSCAN, NG), 256>>>();
    fill_kernel<<<dim3(256, NG), 256>>>(e1, e2, e3);
    convert_kernel<<<dim3(516, NG), 256>>>(x1, x2, x3, W1, W2, W3);
    gather_kernel<<<dim3((NN + 7) / 8, NG), 256>>>();
    gemm_kernel<<<dim3(NT128, NG), 256, SMB_TOT>>>(b1, b2, b3);
    finalize_kernel<<<1, DD>>>(a1w, a1b, a2w, a2b, a3w, a3b, f1w, f1b, f2w, f2b, out);
}